// round 7
// baseline (speedup 1.0000x reference)
#include <cuda_runtime.h>
#include <cuda_bf16.h>
#include <cstdint>

#define GR 8
#define BATCH 32
#define TT 512
#define ROWS 384          // 3 * 128
#define PADW 386          // phase-1 weight smem row stride (floats)
#define XROW 132          // phase-1 x smem row stride (floats)

typedef unsigned long long ull;

// 201 MB scratch for gx[t][g][o][b]
__device__ float g_gx[(size_t)TT * GR * ROWS * BATCH];

__device__ __forceinline__ ull pk(float lo, float hi) {
    ull r;
    asm("mov.b64 %0, {%1, %2};" : "=l"(r) : "f"(lo), "f"(hi));
    return r;
}
__device__ __forceinline__ float2 up(ull v) {
    float2 r;
    asm("mov.b64 {%0, %1}, %2;" : "=f"(r.x), "=f"(r.y) : "l"(v));
    return r;
}
__device__ __forceinline__ void fma2(ull& d, ull a, ull b) {
    asm("fma.rn.f32x2 %0, %1, %2, %0;" : "+l"(d) : "l"(a), "l"(b));
}
__device__ __forceinline__ float sigm(float x) {
    return __fdividef(1.0f, 1.0f + __expf(-x));
}
__device__ __forceinline__ float tanh_(float x) {
    return 1.0f - __fdividef(2.0f, __expf(2.0f * x) + 1.0f);
}
__device__ __forceinline__ float hadd(ull v) {
    float2 u = up(v);
    return u.x + u.y;
}
__device__ __forceinline__ unsigned sptr(const void* p) {
    return (unsigned)__cvta_generic_to_shared(p);
}
__device__ __forceinline__ void cpa8(unsigned d, const void* s) {
    asm volatile("cp.async.ca.shared.global [%0], [%1], 8;" :: "r"(d), "l"(s));
}
__device__ __forceinline__ void cpa16(unsigned d, const void* s) {
    asm volatile("cp.async.cg.shared.global [%0], [%1], 16;" :: "r"(d), "l"(s));
}
__device__ __forceinline__ void cpcommit() { asm volatile("cp.async.commit_group;" ::: "memory"); }
__device__ __forceinline__ void cpwait0()  { asm volatile("cp.async.wait_group 0;" ::: "memory"); }
__device__ __forceinline__ void cpwait1()  { asm volatile("cp.async.wait_group 1;" ::: "memory"); }

// ============================================================================
// Phase 1: gx[t][g][o][b] (unchanged from R4)
// ============================================================================
__global__ void __launch_bounds__(512, 1)
gx_kernel(const float* __restrict__ x,
          const float* __restrict__ W_ih,
          const float* __restrict__ b_ih)
{
    extern __shared__ float sm[];
    float* Ws = sm;                       // [128][PADW]  W[k][o]
    float* Xs = sm + 128 * PADW;          // [2][32][XROW] x[b][k]

    const int g  = blockIdx.x & 7;
    const int tb = blockIdx.x >> 3;
    const int tid = threadIdx.x;

    const float* Wg = W_ih + (size_t)g * ROWS * 128;
    for (int idx = tid; idx < ROWS * 128; idx += 512) {
        int o = idx >> 7, k = idx & 127;
        Ws[k * PADW + o] = Wg[idx];
    }

    const int w    = tid >> 5;
    const int lane = tid & 31;
    const int rsub = lane >> 3;
    const int bq   = lane & 7;
    const int ro   = w * 24 + rsub * 6;

    float bias[6];
#pragma unroll
    for (int i = 0; i < 6; i++) bias[i] = b_ih[g * ROWS + ro + i];

    {
        const int t0 = tb * 32;
#pragma unroll
        for (int r = 0; r < 2; r++) {
            int c = tid + r * 512;
            int b = c >> 5, kq = c & 31;
            cpa16(sptr(Xs + b * XROW + kq * 4),
                  x + ((size_t)b * TT + t0) * 1024 + g * 128 + kq * 4);
        }
    }
    cpcommit();

    for (int tt = 0; tt < 32; tt++) {
        const int t = tb * 32 + tt;
        const float* Xc = Xs + (tt & 1) * (32 * XROW);

        cpwait0();
        __syncthreads();

        if (tt < 31) {
            float* Xn = Xs + ((tt + 1) & 1) * (32 * XROW);
#pragma unroll
            for (int r = 0; r < 2; r++) {
                int c = tid + r * 512;
                int b = c >> 5, kq = c & 31;
                cpa16(sptr(Xn + b * XROW + kq * 4),
                      x + ((size_t)b * TT + t + 1) * 1024 + g * 128 + kq * 4);
            }
        }
        cpcommit();

        ull acc[3][4];
#pragma unroll
        for (int p = 0; p < 3; p++) {
            ull binit = pk(bias[2 * p], bias[2 * p + 1]);
#pragma unroll
            for (int i = 0; i < 4; i++) acc[p][i] = binit;
        }

#pragma unroll 4
        for (int k = 0; k < 128; k++) {
            const float* wb = Ws + k * PADW + ro;
            ull w0 = *(const ull*)(wb);
            ull w1 = *(const ull*)(wb + 2);
            ull w2 = *(const ull*)(wb + 4);
            float x0 = Xc[(bq     ) * XROW + k];
            float x1 = Xc[(bq +  8) * XROW + k];
            float x2 = Xc[(bq + 16) * XROW + k];
            float x3 = Xc[(bq + 24) * XROW + k];
            ull d0 = pk(x0, x0), d1 = pk(x1, x1), d2 = pk(x2, x2), d3 = pk(x3, x3);
            fma2(acc[0][0], w0, d0); fma2(acc[0][1], w0, d1);
            fma2(acc[0][2], w0, d2); fma2(acc[0][3], w0, d3);
            fma2(acc[1][0], w1, d0); fma2(acc[1][1], w1, d1);
            fma2(acc[1][2], w1, d2); fma2(acc[1][3], w1, d3);
            fma2(acc[2][0], w2, d0); fma2(acc[2][1], w2, d1);
            fma2(acc[2][2], w2, d2); fma2(acc[2][3], w2, d3);
        }

        float* outp = g_gx + ((size_t)t * GR + g) * ROWS * BATCH;
#pragma unroll
        for (int p = 0; p < 3; p++) {
#pragma unroll
            for (int i = 0; i < 4; i++) {
                float2 u = up(acc[p][i]);
                outp[(ro + 2 * p)     * BATCH + bq + 8 * i] = u.x;
                outp[(ro + 2 * p + 1) * BATCH + bq + 8 * i] = u.y;
            }
        }
    }
}

// ============================================================================
// Phase 2: recurrence. 128 CTAs = (g, bp). 512 threads:
//   q  = tid & 7   (k-chunk of 16 floats, IN LANE BITS: 8 distinct h-address
//                   groups per warp -> h LDS.128s carry 2x the useful bytes
//                   of R4's 4-group layout; half the LDS instruction count)
//   jj = tid >> 3  (0..63) -> thread owns output units jA=jj, jB=jj+64
// W_hh register-resident: 6 rows x 8 f32x2 pairs = 96 regs. 12 accumulators.
// Reduce-scatter over the 8 q-lanes: 3 shfl rounds (j-half, batch, role);
// each lane ends with complete r,z,n for one (j, b); role lane 0 writes h,
// role lane 1 writes out. Biases in smem. cp.async gx ring as R4.
// ============================================================================
__global__ void __launch_bounds__(512, 1)
gru_kernel(const float* __restrict__ state,
           const float* __restrict__ W_hh,
           const float* __restrict__ b_hh,
           float* __restrict__ out)
{
    __shared__ __align__(16) float Hb0[2][128];
    __shared__ __align__(16) float Hb1[2][128];
    __shared__ __align__(16) float Gs[3][ROWS * 2];   // gx ring [buf][o*2+b]
    __shared__ float Bs[ROWS];

    const int g   = blockIdx.x >> 4;
    const int bp  = blockIdx.x & 15;
    const int tid = threadIdx.x;
    const int q   = tid & 7;        // k-chunk
    const int jj  = tid >> 3;       // 0..63
    const int b0  = bp * 2;

    // ---- weights: rows {jA, 128+jA, 256+jA, jB, 128+jB, 256+jB},
    //      cols [16q, 16q+16) as 8 f32x2 k-pairs each ----
    ull w[6][8];
    {
        const float* base = W_hh + (size_t)g * ROWS * 128 + q * 16;
#pragma unroll
        for (int rr = 0; rr < 6; rr++) {
            const int row = (rr % 3) * 128 + (rr / 3) * 64 + jj;
            const float* pr = base + (size_t)row * 128;
#pragma unroll
            for (int i = 0; i < 4; i++) {
                ulonglong2 v = *(const ulonglong2*)(pr + i * 4);
                w[rr][2 * i] = v.x; w[rr][2 * i + 1] = v.y;
            }
        }
    }

    // biases -> smem
    for (int i = tid; i < ROWS; i += 512) Bs[i] = b_hh[g * ROWS + i];

    if (tid < 128) {
        Hb0[0][tid] = state[((size_t)g * 32 + b0) * 128 + tid];
        Hb1[0][tid] = state[((size_t)g * 32 + b0 + 1) * 128 + tid];
    }

    const size_t stride_t = (size_t)GR * ROWS * BATCH;
    const float* gx0 = g_gx + (size_t)g * ROWS * BATCH + b0;
    const float* gxt = gx0 + (size_t)tid * BATCH;

    if (tid < ROWS) cpa8(sptr(&Gs[0][tid * 2]), gxt);
    cpcommit();
    if (tid < ROWS) cpa8(sptr(&Gs[1][tid * 2]), gxt + stride_t);
    cpcommit();
    gxt += 2 * stride_t;
    cpwait1();
    __syncthreads();

    // final ownership after reduce-scatter:
    const int myjh = q >> 2;              // 0: jA-set, 1: jB-set
    const int myb  = (q >> 1) & 1;        // batch within pair
    const int role = q & 1;               // 0: write h, 1: write out
    const int myj  = myjh * 64 + jj;
    float* outp = out + ((size_t)(b0 + myb) * TT) * 1024 + g * 128 + myj;

    const int qo = q * 16;
    int p = 0, cb = 0;

    for (int t = 0; t < TT; t++) {
        // stage gx for t+2
        {
            int nb = cb + 2; if (nb >= 3) nb -= 3;
            if (t + 2 < TT && tid < ROWS)
                cpa8(sptr(&Gs[nb][tid * 2]), gxt);
            cpcommit();
            gxt += stride_t;
        }

        const float* H0 = Hb0[p];
        const float* H1 = Hb1[p];

        ull a[6][2];   // [row rr][batch]
#pragma unroll
        for (int rr = 0; rr < 6; rr++) { a[rr][0] = 0; a[rr][1] = 0; }

#pragma unroll
        for (int i = 0; i < 4; i++) {
            ulonglong2 h0 = *(const ulonglong2*)(H0 + qo + i * 4);
            ulonglong2 h1 = *(const ulonglong2*)(H1 + qo + i * 4);
#pragma unroll
            for (int rr = 0; rr < 6; rr++) {
                fma2(a[rr][0], w[rr][2 * i],     h0.x);
                fma2(a[rr][1], w[rr][2 * i],     h1.x);
                fma2(a[rr][0], w[rr][2 * i + 1], h0.y);
                fma2(a[rr][1], w[rr][2 * i + 1], h1.y);
            }
        }

        // collapse packed halves: s[rr][b]
        float s[6][2];
#pragma unroll
        for (int rr = 0; rr < 6; rr++) {
            s[rr][0] = hadd(a[rr][0]);
            s[rr][1] = hadd(a[rr][1]);
        }

        // --- reduce-scatter over 8 q-lanes ---
        // round 1 (xor 4): keep my j-half's 6 values (3 gates x 2 batches)
        float k6[6];
        {
            const int lo = myjh ? 3 : 0;     // rows to SEND (other half) start
            const int ke = myjh ? 3 : 0;     // rows to KEEP start = myjh*3
#pragma unroll
            for (int i = 0; i < 3; i++) {
#pragma unroll
                for (int b = 0; b < 2; b++) {
                    float snd = s[(myjh ? 0 : 3) + i][b];
                    float rcv = __shfl_xor_sync(0xffffffffu, snd, 4);
                    k6[i * 2 + b] = s[ke + i][b] + rcv;
                }
            }
            (void)lo;
        }
        // round 2 (xor 2): keep my batch's 3 gates
        float k3[3];
#pragma unroll
        for (int i = 0; i < 3; i++) {
            float snd = k6[i * 2 + (myb ^ 1)];
            float rcv = __shfl_xor_sync(0xffffffffu, snd, 2);
            k3[i] = k6[i * 2 + myb] + rcv;
        }
        // round 3 (xor 1): full sum of r,z,n (both role lanes get all 3)
        float kr = k3[0] + __shfl_xor_sync(0xffffffffu, k3[0], 1);
        float kz = k3[1] + __shfl_xor_sync(0xffffffffu, k3[1], 1);
        float kn = k3[2] + __shfl_xor_sync(0xffffffffu, k3[2], 1);

        // gates for (myj, myb)
        const float* Gc = Gs[cb];
        float gr_ = Gc[(myj)       * 2 + myb];
        float gz_ = Gc[(128 + myj) * 2 + myb];
        float gn_ = Gc[(256 + myj) * 2 + myb];
        float hold = (myb ? Hb1[p] : Hb0[p])[myj];

        float r = sigm(gr_ + kr + Bs[myj]);
        float z = sigm(gz_ + kz + Bs[128 + myj]);
        float n = tanh_(gn_ + r * (kn + Bs[256 + myj]));
        float hn = n + z * (hold - n);

        const int np = p ^ 1;
        if (role == 0) {
            (myb ? Hb1[np] : Hb0[np])[myj] = hn;
        } else {
            *outp = hn;
        }
        outp += 1024;

        cpwait1();
        __syncthreads();
        p = np;
        cb = cb + 1; if (cb >= 3) cb -= 3;
    }

    // h_out[g][b][j] appended after y
    if (role == 0) {
        float* hop = out + (size_t)BATCH * TT * 1024;
        hop[((size_t)g * 32 + b0 + myb) * 128 + myj] = (myb ? Hb1[p] : Hb0[p])[myj];
    }
}

extern "C" void kernel_launch(void* const* d_in, const int* in_sizes, int n_in,
                              void* d_out, int out_size)
{
    const float* x     = (const float*)d_in[0];
    const float* state = (const float*)d_in[1];
    const float* W_ih  = (const float*)d_in[2];
    const float* W_hh  = (const float*)d_in[3];
    const float* b_ih  = (const float*)d_in[4];
    const float* b_hh  = (const float*)d_in[5];
    float* out = (float*)d_out;

    const int smem1 = (128 * PADW + 2 * 32 * XROW) * 4;   // 231,424 B

    cudaFuncSetAttribute(gx_kernel, cudaFuncAttributeMaxDynamicSharedMemorySize, smem1);

    gx_kernel<<<128, 512, smem1>>>(x, W_ih, b_ih);
    gru_kernel<<<128, 512>>>(state, W_hh, b_hh, out);
}

// round 8
// speedup vs baseline: 1.3049x; 1.3049x over previous
#include <cuda_runtime.h>
#include <cuda_bf16.h>
#include <cstdint>

#define GR 8
#define BATCH 32
#define TT 512
#define ROWS 384          // 3 * 128
#define PADW 386          // phase-1 weight smem row stride (floats)
#define XROW 132          // phase-1 x smem row stride (floats)

typedef unsigned long long ull;

// 201 MB scratch for gx[t][g][o][b]
__device__ float g_gx[(size_t)TT * GR * ROWS * BATCH];

__device__ __forceinline__ ull pk(float lo, float hi) {
    ull r;
    asm("mov.b64 %0, {%1, %2};" : "=l"(r) : "f"(lo), "f"(hi));
    return r;
}
__device__ __forceinline__ float2 up(ull v) {
    float2 r;
    asm("mov.b64 {%0, %1}, %2;" : "=f"(r.x), "=f"(r.y) : "l"(v));
    return r;
}
__device__ __forceinline__ void fma2(ull& d, ull a, ull b) {
    asm("fma.rn.f32x2 %0, %1, %2, %0;" : "+l"(d) : "l"(a), "l"(b));
}
__device__ __forceinline__ float sigm(float x) {
    return __fdividef(1.0f, 1.0f + __expf(-x));
}
__device__ __forceinline__ float tanh_(float x) {
    return 1.0f - __fdividef(2.0f, __expf(2.0f * x) + 1.0f);
}
__device__ __forceinline__ float hadd(ull v) {
    float2 u = up(v);
    return u.x + u.y;
}
__device__ __forceinline__ unsigned sptr(const void* p) {
    return (unsigned)__cvta_generic_to_shared(p);
}
__device__ __forceinline__ void cpa8(unsigned d, const void* s) {
    asm volatile("cp.async.ca.shared.global [%0], [%1], 8;" :: "r"(d), "l"(s));
}
__device__ __forceinline__ void cpa16(unsigned d, const void* s) {
    asm volatile("cp.async.cg.shared.global [%0], [%1], 16;" :: "r"(d), "l"(s));
}
__device__ __forceinline__ void cpcommit() { asm volatile("cp.async.commit_group;" ::: "memory"); }
__device__ __forceinline__ void cpwait0()  { asm volatile("cp.async.wait_group 0;" ::: "memory"); }
__device__ __forceinline__ void cpwait1()  { asm volatile("cp.async.wait_group 1;" ::: "memory"); }

// ============================================================================
// Phase 1: gx[t][g][o][b] (unchanged from R4)
// ============================================================================
__global__ void __launch_bounds__(512, 1)
gx_kernel(const float* __restrict__ x,
          const float* __restrict__ W_ih,
          const float* __restrict__ b_ih)
{
    extern __shared__ float sm[];
    float* Ws = sm;                       // [128][PADW]  W[k][o]
    float* Xs = sm + 128 * PADW;          // [2][32][XROW] x[b][k]

    const int g  = blockIdx.x & 7;
    const int tb = blockIdx.x >> 3;
    const int tid = threadIdx.x;

    const float* Wg = W_ih + (size_t)g * ROWS * 128;
    for (int idx = tid; idx < ROWS * 128; idx += 512) {
        int o = idx >> 7, k = idx & 127;
        Ws[k * PADW + o] = Wg[idx];
    }

    const int w    = tid >> 5;
    const int lane = tid & 31;
    const int rsub = lane >> 3;
    const int bq   = lane & 7;
    const int ro   = w * 24 + rsub * 6;

    float bias[6];
#pragma unroll
    for (int i = 0; i < 6; i++) bias[i] = b_ih[g * ROWS + ro + i];

    {
        const int t0 = tb * 32;
#pragma unroll
        for (int r = 0; r < 2; r++) {
            int c = tid + r * 512;
            int b = c >> 5, kq = c & 31;
            cpa16(sptr(Xs + b * XROW + kq * 4),
                  x + ((size_t)b * TT + t0) * 1024 + g * 128 + kq * 4);
        }
    }
    cpcommit();

    for (int tt = 0; tt < 32; tt++) {
        const int t = tb * 32 + tt;
        const float* Xc = Xs + (tt & 1) * (32 * XROW);

        cpwait0();
        __syncthreads();

        if (tt < 31) {
            float* Xn = Xs + ((tt + 1) & 1) * (32 * XROW);
#pragma unroll
            for (int r = 0; r < 2; r++) {
                int c = tid + r * 512;
                int b = c >> 5, kq = c & 31;
                cpa16(sptr(Xn + b * XROW + kq * 4),
                      x + ((size_t)b * TT + t + 1) * 1024 + g * 128 + kq * 4);
            }
        }
        cpcommit();

        ull acc[3][4];
#pragma unroll
        for (int p = 0; p < 3; p++) {
            ull binit = pk(bias[2 * p], bias[2 * p + 1]);
#pragma unroll
            for (int i = 0; i < 4; i++) acc[p][i] = binit;
        }

#pragma unroll 4
        for (int k = 0; k < 128; k++) {
            const float* wb = Ws + k * PADW + ro;
            ull w0 = *(const ull*)(wb);
            ull w1 = *(const ull*)(wb + 2);
            ull w2 = *(const ull*)(wb + 4);
            float x0 = Xc[(bq     ) * XROW + k];
            float x1 = Xc[(bq +  8) * XROW + k];
            float x2 = Xc[(bq + 16) * XROW + k];
            float x3 = Xc[(bq + 24) * XROW + k];
            ull d0 = pk(x0, x0), d1 = pk(x1, x1), d2 = pk(x2, x2), d3 = pk(x3, x3);
            fma2(acc[0][0], w0, d0); fma2(acc[0][1], w0, d1);
            fma2(acc[0][2], w0, d2); fma2(acc[0][3], w0, d3);
            fma2(acc[1][0], w1, d0); fma2(acc[1][1], w1, d1);
            fma2(acc[1][2], w1, d2); fma2(acc[1][3], w1, d3);
            fma2(acc[2][0], w2, d0); fma2(acc[2][1], w2, d1);
            fma2(acc[2][2], w2, d2); fma2(acc[2][3], w2, d3);
        }

        float* outp = g_gx + ((size_t)t * GR + g) * ROWS * BATCH;
#pragma unroll
        for (int p = 0; p < 3; p++) {
#pragma unroll
            for (int i = 0; i < 4; i++) {
                float2 u = up(acc[p][i]);
                outp[(ro + 2 * p)     * BATCH + bq + 8 * i] = u.x;
                outp[(ro + 2 * p + 1) * BATCH + bq + 8 * i] = u.y;
            }
        }
    }
}

// ============================================================================
// Phase 2: recurrence. 128 CTAs = (g, bp). 512 threads:
//   q  = tid & 7  (k-chunk of 16 floats, in lane bits: 8 distinct 16B address
//                  groups per warp -> every h LDS.128 wavefront carries useful
//                  bytes; 8 LDS.128/thread/step total)
//   jj = tid >> 3 (0..63) -> thread owns rows for jA=jj and jB=jj+64
// TWO-PASS batches: batch b0 then b1 reuse the SAME 6 accumulators
// (acc 12 regs vs R7's 24 -> no heavy spilling; weights 96 regs).
// Per pass: 3-shfl j-half scatter + 6-shfl bfly allreduce over 4 lanes;
// role lane (q&3)==0 writes h, ==1 writes out. Biases in smem; cp.async gx
// ring; ping-pong h; one barrier per step.
// ============================================================================
__global__ void __launch_bounds__(512, 1)
gru_kernel(const float* __restrict__ state,
           const float* __restrict__ W_hh,
           const float* __restrict__ b_hh,
           float* __restrict__ out)
{
    __shared__ __align__(16) float Hb[2][2][128];     // [batch][pingpong][j]
    __shared__ __align__(16) float Gs[3][ROWS * 2];   // gx ring [buf][o*2+b]
    __shared__ float Bs[ROWS];

    const int g   = blockIdx.x >> 4;
    const int bp  = blockIdx.x & 15;
    const int tid = threadIdx.x;
    const int q   = tid & 7;
    const int jj  = tid >> 3;
    const int b0  = bp * 2;

    // weights: rows {jA, 128+jA, 256+jA, jB, 128+jB, 256+jB}, cols [16q,16q+16)
    ull w[6][8];
    {
        const float* base = W_hh + (size_t)g * ROWS * 128 + q * 16;
#pragma unroll
        for (int rr = 0; rr < 6; rr++) {
            const int row = (rr % 3) * 128 + (rr / 3) * 64 + jj;
            const float* pr = base + (size_t)row * 128;
#pragma unroll
            for (int i = 0; i < 4; i++) {
                ulonglong2 v = *(const ulonglong2*)(pr + i * 4);
                w[rr][2 * i] = v.x; w[rr][2 * i + 1] = v.y;
            }
        }
    }

    for (int i = tid; i < ROWS; i += 512) Bs[i] = b_hh[g * ROWS + i];

    if (tid < 128) {
        Hb[0][0][tid] = state[((size_t)g * 32 + b0) * 128 + tid];
        Hb[1][0][tid] = state[((size_t)g * 32 + b0 + 1) * 128 + tid];
    }

    const size_t stride_t = (size_t)GR * ROWS * BATCH;
    const float* gx0 = g_gx + (size_t)g * ROWS * BATCH + b0;
    const float* gxt = gx0 + (size_t)tid * BATCH;

    if (tid < ROWS) cpa8(sptr(&Gs[0][tid * 2]), gxt);
    cpcommit();
    if (tid < ROWS) cpa8(sptr(&Gs[1][tid * 2]), gxt + stride_t);
    cpcommit();
    gxt += 2 * stride_t;
    cpwait1();
    __syncthreads();

    const int myjh = q >> 2;             // which j-half I keep in the scatter
    const int myj  = myjh * 64 + jj;
    const int role = q & 3;              // 0: write h, 1: write out
    const int qo   = q * 16;

    int p = 0, cb = 0;

    for (int t = 0; t < TT; t++) {
        // stage gx for t+2
        {
            int nb = cb + 2; if (nb >= 3) nb -= 3;
            if (t + 2 < TT && tid < ROWS)
                cpa8(sptr(&Gs[nb][tid * 2]), gxt);
            cpcommit();
            gxt += stride_t;
        }

        const int np = p ^ 1;
        const float* Gc = Gs[cb];
        const float bsr = Bs[myj], bsz = Bs[128 + myj], bsn = Bs[256 + myj];

#pragma unroll
        for (int bb = 0; bb < 2; bb++) {
            const float* H = Hb[bb][p];

            ull a0 = 0, a1 = 0, a2 = 0, a3 = 0, a4 = 0, a5 = 0;
#pragma unroll
            for (int i = 0; i < 4; i++) {
                ulonglong2 h = *(const ulonglong2*)(H + qo + i * 4);
                fma2(a0, w[0][2 * i],     h.x);
                fma2(a1, w[1][2 * i],     h.x);
                fma2(a2, w[2][2 * i],     h.x);
                fma2(a3, w[3][2 * i],     h.x);
                fma2(a4, w[4][2 * i],     h.x);
                fma2(a5, w[5][2 * i],     h.x);
                fma2(a0, w[0][2 * i + 1], h.y);
                fma2(a1, w[1][2 * i + 1], h.y);
                fma2(a2, w[2][2 * i + 1], h.y);
                fma2(a3, w[3][2 * i + 1], h.y);
                fma2(a4, w[4][2 * i + 1], h.y);
                fma2(a5, w[5][2 * i + 1], h.y);
            }

            float s[6];
            s[0] = hadd(a0); s[1] = hadd(a1); s[2] = hadd(a2);
            s[3] = hadd(a3); s[4] = hadd(a4); s[5] = hadd(a5);

            // scatter round (xor 4): keep my j-half's 3 gate partials
            float k3[3];
#pragma unroll
            for (int i = 0; i < 3; i++) {
                float snd = s[3 * (1 - myjh) + i];
                float rcv = __shfl_xor_sync(0xffffffffu, snd, 4);
                k3[i] = s[3 * myjh + i] + rcv;
            }
            // bfly allreduce over remaining 4 lanes
#pragma unroll
            for (int i = 0; i < 3; i++) {
                k3[i] += __shfl_xor_sync(0xffffffffu, k3[i], 2);
                k3[i] += __shfl_xor_sync(0xffffffffu, k3[i], 1);
            }

            float gr_ = Gc[(myj)       * 2 + bb];
            float gz_ = Gc[(128 + myj) * 2 + bb];
            float gn_ = Gc[(256 + myj) * 2 + bb];
            float hold = Hb[bb][p][myj];

            float r = sigm(gr_ + k3[0] + bsr);
            float z = sigm(gz_ + k3[1] + bsz);
            float n = tanh_(gn_ + r * (k3[2] + bsn));
            float hn = n + z * (hold - n);

            if (role == 0) {
                Hb[bb][np][myj] = hn;
            } else if (role == 1) {
                out[((size_t)(b0 + bb) * TT + t) * 1024 + g * 128 + myj] = hn;
            }
        }

        cpwait1();
        __syncthreads();
        p = np;
        cb = cb + 1; if (cb >= 3) cb -= 3;
    }

    // h_out[g][b][j] appended after y
    if (role == 0) {
        float* hop = out + (size_t)BATCH * TT * 1024;
        hop[((size_t)g * 32 + b0 + (myjh ? 1 : 0)) * 128 + 0] = hop[((size_t)g * 32 + b0 + (myjh ? 1 : 0)) * 128 + 0];
    }
    if (tid < 128) {
        float* hop = out + (size_t)BATCH * TT * 1024;
        hop[((size_t)g * 32 + b0) * 128 + tid]     = Hb[0][p][tid];
        hop[((size_t)g * 32 + b0 + 1) * 128 + tid] = Hb[1][p][tid];
    }
}

extern "C" void kernel_launch(void* const* d_in, const int* in_sizes, int n_in,
                              void* d_out, int out_size)
{
    const float* x     = (const float*)d_in[0];
    const float* state = (const float*)d_in[1];
    const float* W_ih  = (const float*)d_in[2];
    const float* W_hh  = (const float*)d_in[3];
    const float* b_ih  = (const float*)d_in[4];
    const float* b_hh  = (const float*)d_in[5];
    float* out = (float*)d_out;

    const int smem1 = (128 * PADW + 2 * 32 * XROW) * 4;   // 231,424 B

    cudaFuncSetAttribute(gx_kernel, cudaFuncAttributeMaxDynamicSharedMemorySize, smem1);

    gx_kernel<<<128, 512, smem1>>>(x, W_ih, b_ih);
    gru_kernel<<<128, 512>>>(state, W_hh, b_hh, out);
}

// round 10
// speedup vs baseline: 2.2789x; 1.7464x over previous
#include <cuda_runtime.h>
#include <cuda_bf16.h>
#include <cstdint>

#define GR 8
#define BATCH 32
#define TT 512
#define ROWS 384          // 3 * 128
#define KC 384            // cat-K
#define APAD 392          // smem row stride (bf16) for A/B tiles (16B-aligned, conflict-free ldmatrix)

typedef unsigned long long ull;

// scratch: gx fp32 (201MB), split-bf16 operands
__device__ float g_gx[(size_t)TT * GR * ROWS * BATCH];
__device__ __nv_bfloat16 g_acat[(size_t)GR * ROWS * KC];         // [g][o][k]
__device__ __nv_bfloat16 g_xcat[(size_t)TT * GR * BATCH * KC];   // [t][g][b][k]

__device__ __forceinline__ ull pk(float lo, float hi) {
    ull r;
    asm("mov.b64 %0, {%1, %2};" : "=l"(r) : "f"(lo), "f"(hi));
    return r;
}
__device__ __forceinline__ float2 up(ull v) {
    float2 r;
    asm("mov.b64 {%0, %1}, %2;" : "=f"(r.x), "=f"(r.y) : "l"(v));
    return r;
}
__device__ __forceinline__ void fma2(ull& d, ull a, ull b) {
    asm("fma.rn.f32x2 %0, %1, %2, %0;" : "+l"(d) : "l"(a), "l"(b));
}
__device__ __forceinline__ float sigm(float x) {
    return __fdividef(1.0f, 1.0f + __expf(-x));
}
__device__ __forceinline__ float tanh_(float x) {
    return 1.0f - __fdividef(2.0f, __expf(2.0f * x) + 1.0f);
}
__device__ __forceinline__ float hadd(ull v) {
    float2 u = up(v);
    return u.x + u.y;
}
__device__ __forceinline__ unsigned sptr(const void* p) {
    return (unsigned)__cvta_generic_to_shared(p);
}
__device__ __forceinline__ void cpa8(unsigned d, const void* s) {
    asm volatile("cp.async.ca.shared.global [%0], [%1], 8;" :: "r"(d), "l"(s));
}
__device__ __forceinline__ void cpa16(unsigned d, const void* s) {
    asm volatile("cp.async.cg.shared.global [%0], [%1], 16;" :: "r"(d), "l"(s));
}
__device__ __forceinline__ void cpcommit() { asm volatile("cp.async.commit_group;" ::: "memory"); }
__device__ __forceinline__ void cpwait1()  { asm volatile("cp.async.wait_group 1;" ::: "memory"); }

__device__ __forceinline__ void ldm4(uint32_t* r, unsigned addr) {
    asm volatile("ldmatrix.sync.aligned.m8n8.x4.shared.b16 {%0,%1,%2,%3}, [%4];"
                 : "=r"(r[0]), "=r"(r[1]), "=r"(r[2]), "=r"(r[3]) : "r"(addr));
}
__device__ __forceinline__ void mma16816(float* d, const uint32_t* a, const uint32_t* b) {
    asm volatile(
        "mma.sync.aligned.m16n8k16.row.col.f32.bf16.bf16.f32 "
        "{%0,%1,%2,%3}, {%4,%5,%6,%7}, {%8,%9}, {%0,%1,%2,%3};"
        : "+f"(d[0]), "+f"(d[1]), "+f"(d[2]), "+f"(d[3])
        : "r"(a[0]), "r"(a[1]), "r"(a[2]), "r"(a[3]), "r"(b[0]), "r"(b[1]));
}

// ============================================================================
// prep_w: A_cat[g][o] = [bf16(W) | bf16(W) | Wlo] over k
// ============================================================================
__global__ void prep_w(const float* __restrict__ W_ih)
{
    int idx = blockIdx.x * 256 + threadIdx.x;
    if (idx >= GR * ROWS * 128) return;
    float v = W_ih[idx];
    int k = idx & 127;
    int go = idx >> 7;
    __nv_bfloat16 hi = __float2bfloat16(v);
    __nv_bfloat16 lo = __float2bfloat16(v - __bfloat162float(hi));
    __nv_bfloat16* dst = g_acat + (size_t)go * KC;
    dst[k] = hi; dst[128 + k] = hi; dst[256 + k] = lo;
}

// ============================================================================
// prep_x: X_cat[t][g][b] = [xhi | xlo | xhi] over k
// ============================================================================
__global__ void prep_x(const float* __restrict__ x)
{
    int idx = blockIdx.x * 256 + threadIdx.x;          // 16777216
    float v = x[idx];
    int k = idx & 127;
    int g = (idx >> 7) & 7;
    int t = (idx >> 10) & 511;
    int b = idx >> 19;
    __nv_bfloat16 hi = __float2bfloat16(v);
    __nv_bfloat16 lo = __float2bfloat16(v - __bfloat162float(hi));
    __nv_bfloat16* dst = g_xcat + ((((size_t)t * GR + g) * BATCH) + b) * KC;
    dst[k] = hi; dst[128 + k] = lo; dst[256 + k] = hi;
}

// ============================================================================
// gx_mma: CTA (g, mt, tb): D[128 x 32] = A[128 x 384] * X[32 x 384]^T for 32 t.
// mma.sync m16n8k16 bf16, register accumulators, A in smem (staged once),
// B double-buffered via cp.async. 256 threads = warp grid 4(m) x 2(n).
// ============================================================================
#define A_SM_BYTES (128 * APAD * 2)      // 100,352
#define B_SM_BYTES (32 * APAD * 2)       // 25,088

__global__ void __launch_bounds__(256, 1)
gx_mma(const float* __restrict__ b_ih)
{
    extern __shared__ __align__(1024) char smx[];      // A | B0 | B1
    const int bx  = blockIdx.x;                        // 8g * 48
    const int g   = bx & 7;
    const int r   = bx >> 3;
    const int mt  = r % 3;
    const int tb  = r / 3;
    const int tid = threadIdx.x;
    const int wid = tid >> 5;
    const int lane = tid & 31;
    const int wm  = wid >> 1;           // 0..3 (m)
    const int wn  = wid & 1;            // 0..1 (n)

    const uint32_t Abase = sptr(smx);
    const uint32_t Bbase = Abase + A_SM_BYTES;

    // ---- stage A once ----
    {
        const __nv_bfloat16* src = g_acat + ((size_t)g * ROWS + mt * 128) * KC;
        for (int c = tid; c < 128 * 48; c += 256) {
            int row = c / 48, kc = c % 48;
            cpa16(Abase + row * (APAD * 2) + kc * 16, src + (size_t)row * KC + kc * 8);
        }
    }
    cpcommit();

    // ---- stage B(0) ----
    const __nv_bfloat16* xsrc = g_xcat + ((size_t)(tb * 32) * GR + g) * BATCH * KC;
    {
        for (int c = tid; c < 32 * 48; c += 256) {
            int row = c / 48, kc = c % 48;
            cpa16(Bbase + row * (APAD * 2) + kc * 16, xsrc + (size_t)row * KC + kc * 8);
        }
    }
    cpcommit();

    // lane-invariant ldmatrix offsets
    const uint32_t aoffs = (uint32_t)(wm * 32 + (lane & 15)) * (APAD * 2) + ((lane >> 4) << 3) * 2;
    const uint32_t boffs = (uint32_t)(wn * 16 + ((lane >> 4) << 3) + (lane & 7)) * (APAD * 2)
                         + (((lane >> 3) & 1) << 3) * 2;

    const int gid = lane >> 2;          // D row within 8x8
    const int tg  = lane & 3;

    // biases for my 4 output rows
    const int ob = mt * 128 + wm * 32 + gid;
    float bias[2][2];
    bias[0][0] = b_ih[g * ROWS + ob];
    bias[0][1] = b_ih[g * ROWS + ob + 8];
    bias[1][0] = b_ih[g * ROWS + ob + 16];
    bias[1][1] = b_ih[g * ROWS + ob + 24];

    float* gout = g_gx + ((size_t)(tb * 32) * GR + g) * ROWS * BATCH
                + (size_t)(mt * 128 + wm * 32 + gid) * BATCH + wn * 16 + tg * 2;
    const size_t gstep = (size_t)GR * ROWS * BATCH;

    for (int t = 0; t < 32; t++) {
        // stage B(t+1) — buffer (t+1)&1 was last read at t-1 (guarded by sync below)
        if (t < 31) {
            const __nv_bfloat16* s2 = xsrc + (size_t)(t + 1) * GR * BATCH * KC;
            uint32_t dstb = Bbase + ((t + 1) & 1) * B_SM_BYTES;
            for (int c = tid; c < 32 * 48; c += 256) {
                int row = c / 48, kc = c % 48;
                cpa16(dstb + row * (APAD * 2) + kc * 16, s2 + (size_t)row * KC + kc * 8);
            }
        }
        cpcommit();
        cpwait1();          // B(t) (and A on t=0) complete
        __syncthreads();

        const uint32_t Bt = Bbase + (t & 1) * B_SM_BYTES;

        float d[2][2][4];
#pragma unroll
        for (int i = 0; i < 2; i++)
#pragma unroll
            for (int jn = 0; jn < 2; jn++)
#pragma unroll
                for (int e = 0; e < 4; e++) d[i][jn][e] = 0.f;

#pragma unroll
        for (int ks = 0; ks < 24; ks++) {
            const uint32_t kk = ks * 32;       // bytes: 16 bf16
            uint32_t a0[4], a1[4], bb[4];
            ldm4(a0, Abase + aoffs + kk);
            ldm4(a1, Abase + aoffs + 16 * (APAD * 2) + kk);
            ldm4(bb, Bt + boffs + kk);
            mma16816(d[0][0], a0, bb);
            mma16816(d[0][1], a0, bb + 2);
            mma16816(d[1][0], a1, bb);
            mma16816(d[1][1], a1, bb + 2);
        }

        // epilogue: write gx[t][g][o][b] + bias
        float* op = gout + (size_t)t * gstep;
#pragma unroll
        for (int i = 0; i < 2; i++) {
#pragma unroll
            for (int jn = 0; jn < 2; jn++) {
                float2 v0 = make_float2(d[i][jn][0] + bias[i][0], d[i][jn][1] + bias[i][0]);
                float2 v1 = make_float2(d[i][jn][2] + bias[i][1], d[i][jn][3] + bias[i][1]);
                *(float2*)(op + (size_t)(i * 16) * BATCH + jn * 8)     = v0;
                *(float2*)(op + (size_t)(i * 16 + 8) * BATCH + jn * 8) = v1;
            }
        }
        __syncthreads();    // all reads of B(t) done before next iter overwrites
    }
}

// ============================================================================
// Phase 2: recurrence — R4 VERBATIM (best: 646us).
// ============================================================================
__global__ void __launch_bounds__(512, 1)
gru_kernel(const float* __restrict__ state,
           const float* __restrict__ W_hh,
           const float* __restrict__ b_hh,
           float* __restrict__ out)
{
    __shared__ __align__(16) float Hb0[2][144];
    __shared__ __align__(16) float Hb1[2][144];
    __shared__ __align__(16) float Gs[3][ROWS * 2];

    const int g   = blockIdx.x >> 4;
    const int bp  = blockIdx.x & 15;
    const int tid = threadIdx.x;
    const int j   = tid >> 2;
    const int q   = tid & 3;
    const int b0  = bp * 2;

    ull wr[16], wz[16], wn[16];
    {
        const float* base = W_hh + (size_t)g * ROWS * 128 + q * 32;
        const float* pr = base + (size_t)(j)       * 128;
        const float* pz = base + (size_t)(128 + j) * 128;
        const float* pn = base + (size_t)(256 + j) * 128;
#pragma unroll
        for (int i = 0; i < 8; i++) {
            ulonglong2 a = *(const ulonglong2*)(pr + i * 4);
            wr[2 * i] = a.x; wr[2 * i + 1] = a.y;
            ulonglong2 b = *(const ulonglong2*)(pz + i * 4);
            wz[2 * i] = b.x; wz[2 * i + 1] = b.y;
            ulonglong2 c = *(const ulonglong2*)(pn + i * 4);
            wn[2 * i] = c.x; wn[2 * i + 1] = c.y;
        }
    }

    const float bhr = b_hh[g * ROWS + j];
    const float bhz = b_hh[g * ROWS + 128 + j];
    const float bhn = b_hh[g * ROWS + 256 + j];

    const int jsw = (j >> 5) * 36 + (j & 31);

    if (q == 0) Hb0[0][jsw] = state[((size_t)g * 32 + b0) * 128 + j];
    if (q == 1) Hb1[0][jsw] = state[((size_t)g * 32 + b0 + 1) * 128 + j];

    const size_t stride_t = (size_t)GR * ROWS * BATCH;
    const float* gx0 = g_gx + (size_t)g * ROWS * BATCH + b0;

    const float* gxt = gx0 + (size_t)tid * BATCH;
    if (tid < ROWS) cpa8(sptr(&Gs[0][tid * 2]), gxt);
    cpcommit();
    if (tid < ROWS) cpa8(sptr(&Gs[1][tid * 2]), gxt + stride_t);
    cpcommit();
    gxt += 2 * stride_t;
    cpwait1();
    __syncthreads();

    const int myb = q >> 1;
    float* outp = out + ((size_t)(b0 + myb) * TT) * 1024 + g * 128 + j;

    const int qoff = q * 36;
    int p = 0, cb = 0;

    for (int t = 0; t < TT; t++) {
        {
            int nb = cb + 2; if (nb >= 3) nb -= 3;
            if (t + 2 < TT && tid < ROWS)
                cpa8(sptr(&Gs[nb][tid * 2]), gxt);
            cpcommit();
            gxt += stride_t;
        }

        const float* H0 = Hb0[p];
        const float* H1 = Hb1[p];

        ull ar0 = 0, az0 = 0, an0 = 0;
        ull ar1 = 0, az1 = 0, an1 = 0;

#pragma unroll
        for (int i = 0; i < 8; i++) {
            ulonglong2 h0 = *(const ulonglong2*)(H0 + qoff + i * 4);
            ulonglong2 h1 = *(const ulonglong2*)(H1 + qoff + i * 4);
            fma2(ar0, wr[2 * i],     h0.x);
            fma2(az0, wz[2 * i],     h0.x);
            fma2(an0, wn[2 * i],     h0.x);
            fma2(ar1, wr[2 * i],     h1.x);
            fma2(az1, wz[2 * i],     h1.x);
            fma2(an1, wn[2 * i],     h1.x);
            fma2(ar0, wr[2 * i + 1], h0.y);
            fma2(az0, wz[2 * i + 1], h0.y);
            fma2(an0, wn[2 * i + 1], h0.y);
            fma2(ar1, wr[2 * i + 1], h1.y);
            fma2(az1, wz[2 * i + 1], h1.y);
            fma2(an1, wn[2 * i + 1], h1.y);
        }

        float sr0 = hadd(ar0), sz0 = hadd(az0), sn0 = hadd(an0);
        float sr1 = hadd(ar1), sz1 = hadd(az1), sn1 = hadd(an1);

        const bool hi = (q & 2) != 0;
        float vr = hi ? sr0 : sr1;
        float vz = hi ? sz0 : sz1;
        float vn = hi ? sn0 : sn1;
        float kr = hi ? sr1 : sr0;
        float kz = hi ? sz1 : sz0;
        float kn = hi ? sn1 : sn0;
        kr += __shfl_xor_sync(0xffffffffu, vr, 2);
        kz += __shfl_xor_sync(0xffffffffu, vz, 2);
        kn += __shfl_xor_sync(0xffffffffu, vn, 2);
        kr += __shfl_xor_sync(0xffffffffu, kr, 1);
        kz += __shfl_xor_sync(0xffffffffu, kz, 1);
        kn += __shfl_xor_sync(0xffffffffu, kn, 1);

        const float* Gc = Gs[cb];
        float gr_ = Gc[(j)       * 2 + myb];
        float gz_ = Gc[(128 + j) * 2 + myb];
        float gn_ = Gc[(256 + j) * 2 + myb];
        float hold = (hi ? H1 : H0)[jsw];

        float rr = sigm(gr_ + kr + bhr);
        float zz = sigm(gz_ + kz + bhz);
        float nn = tanh_(gn_ + rr * (kn + bhn));
        float hn = nn + zz * (hold - nn);

        const int np = p ^ 1;
        if (q == 0) {
            Hb0[np][jsw] = hn;
        } else if (q == 2) {
            Hb1[np][jsw] = hn;
        } else {
            *outp = hn;
        }
        outp += 1024;

        cpwait1();
        __syncthreads();
        p = np;
        cb = cb + 1; if (cb >= 3) cb -= 3;
    }

    float* hop = out + (size_t)BATCH * TT * 1024;
    if (q == 0) hop[((size_t)g * 32 + b0) * 128 + j]     = Hb0[p][jsw];
    if (q == 2) hop[((size_t)g * 32 + b0 + 1) * 128 + j] = Hb1[p][jsw];
}

extern "C" void kernel_launch(void* const* d_in, const int* in_sizes, int n_in,
                              void* d_out, int out_size)
{
    const float* x     = (const float*)d_in[0];
    const float* state = (const float*)d_in[1];
    const float* W_ih  = (const float*)d_in[2];
    const float* W_hh  = (const float*)d_in[3];
    const float* b_ih  = (const float*)d_in[4];
    const float* b_hh  = (const float*)d_in[5];
    float* out = (float*)d_out;

    const int smem_mma = A_SM_BYTES + 2 * B_SM_BYTES;   // 150,528
    cudaFuncSetAttribute(gx_mma, cudaFuncAttributeMaxDynamicSharedMemorySize, smem_mma);

    prep_w<<<1536, 256>>>(W_ih);
    prep_x<<<65536, 256>>>(x);
    gx_mma<<<384, 256, smem_mma>>>(b_ih);
    gru_kernel<<<128, 512>>>(state, W_hh, b_hh, out);
}

// round 11
// speedup vs baseline: 2.3249x; 1.0202x over previous
#include <cuda_runtime.h>
#include <cuda_bf16.h>
#include <cstdint>

#define GR 8
#define BATCH 32
#define TT 512
#define ROWS 384          // 3 * 128
#define KC 384            // cat-K
#define APAD 392          // smem row stride (bf16) for A/B tiles

typedef unsigned long long ull;

// scratch: gx fp32 (201MB), split-bf16 A operand
__device__ float g_gx[(size_t)TT * GR * ROWS * BATCH];
__device__ __nv_bfloat16 g_acat[(size_t)GR * ROWS * KC];         // [g][o][k]

__device__ __forceinline__ ull pk(float lo, float hi) {
    ull r;
    asm("mov.b64 %0, {%1, %2};" : "=l"(r) : "f"(lo), "f"(hi));
    return r;
}
__device__ __forceinline__ float2 up(ull v) {
    float2 r;
    asm("mov.b64 {%0, %1}, %2;" : "=f"(r.x), "=f"(r.y) : "l"(v));
    return r;
}
__device__ __forceinline__ void fma2(ull& d, ull a, ull b) {
    asm("fma.rn.f32x2 %0, %1, %2, %0;" : "+l"(d) : "l"(a), "l"(b));
}
__device__ __forceinline__ float sigm(float x) {
    return __fdividef(1.0f, 1.0f + __expf(-x));
}
__device__ __forceinline__ float tanh_(float x) {
    return 1.0f - __fdividef(2.0f, __expf(2.0f * x) + 1.0f);
}
__device__ __forceinline__ float hadd(ull v) {
    float2 u = up(v);
    return u.x + u.y;
}
__device__ __forceinline__ unsigned sptr(const void* p) {
    return (unsigned)__cvta_generic_to_shared(p);
}
__device__ __forceinline__ void cpa8(unsigned d, const void* s) {
    asm volatile("cp.async.ca.shared.global [%0], [%1], 8;" :: "r"(d), "l"(s));
}
__device__ __forceinline__ void cpa16(unsigned d, const void* s) {
    asm volatile("cp.async.cg.shared.global [%0], [%1], 16;" :: "r"(d), "l"(s));
}
__device__ __forceinline__ void cpcommit() { asm volatile("cp.async.commit_group;" ::: "memory"); }
__device__ __forceinline__ void cpwait0()  { asm volatile("cp.async.wait_group 0;" ::: "memory"); }
__device__ __forceinline__ void cpwait1()  { asm volatile("cp.async.wait_group 1;" ::: "memory"); }

__device__ __forceinline__ void ldm4(uint32_t* r, unsigned addr) {
    asm volatile("ldmatrix.sync.aligned.m8n8.x4.shared.b16 {%0,%1,%2,%3}, [%4];"
                 : "=r"(r[0]), "=r"(r[1]), "=r"(r[2]), "=r"(r[3]) : "r"(addr));
}
__device__ __forceinline__ void mma16816(float* d, const uint32_t* a, const uint32_t* b) {
    asm volatile(
        "mma.sync.aligned.m16n8k16.row.col.f32.bf16.bf16.f32 "
        "{%0,%1,%2,%3}, {%4,%5,%6,%7}, {%8,%9}, {%0,%1,%2,%3};"
        : "+f"(d[0]), "+f"(d[1]), "+f"(d[2]), "+f"(d[3])
        : "r"(a[0]), "r"(a[1]), "r"(a[2]), "r"(a[3]), "r"(b[0]), "r"(b[1]));
}
__device__ __forceinline__ uint32_t pkbf(float v0, float v1) {
    __nv_bfloat16 b0 = __float2bfloat16(v0);
    __nv_bfloat16 b1 = __float2bfloat16(v1);
    return (uint32_t)__bfloat16_as_ushort(b0) | ((uint32_t)__bfloat16_as_ushort(b1) << 16);
}

// ============================================================================
// prep_w: A_cat[g][o] = [bf16(W) | bf16(W) | Wlo] over k
// ============================================================================
__global__ void prep_w(const float* __restrict__ W_ih)
{
    int idx = blockIdx.x * 256 + threadIdx.x;
    if (idx >= GR * ROWS * 128) return;
    float v = W_ih[idx];
    int k = idx & 127;
    int go = idx >> 7;
    __nv_bfloat16 hi = __float2bfloat16(v);
    __nv_bfloat16 lo = __float2bfloat16(v - __bfloat162float(hi));
    __nv_bfloat16* dst = g_acat + (size_t)go * KC;
    dst[k] = hi; dst[128 + k] = hi; dst[256 + k] = lo;
}

// ============================================================================
// gx_mma: CTA (g, mt, tb): D[128 x 32] = A[128 x 384] * X[32 x 384]^T for 32 t.
// B tile built IN-KERNEL from fp32 x: thread loads x(t+1) 16 floats via LDG
// (issued before the MMA loop -> latency covered), converts to split-bf16
// [hi | lo | hi], STS into the double-buffered B tile. No g_xcat, no prep_x.
// A staged once via cp.async. 256 threads = warp grid 4(m) x 2(n).
// ============================================================================
#define A_SM_BYTES (128 * APAD * 2)      // 100,352
#define B_SM_BYTES (32 * APAD * 2)       // 25,088

__global__ void __launch_bounds__(256, 1)
gx_mma(const float* __restrict__ x, const float* __restrict__ b_ih)
{
    extern __shared__ __align__(1024) char smx[];      // A | B0 | B1
    const int bx  = blockIdx.x;                        // 8g * 48
    const int g   = bx & 7;
    const int r   = bx >> 3;
    const int mt  = r % 3;
    const int tb  = r / 3;
    const int tid = threadIdx.x;
    const int wid = tid >> 5;
    const int lane = tid & 31;
    const int wm  = wid >> 1;           // 0..3 (m)
    const int wn  = wid & 1;            // 0..1 (n)

    const uint32_t Abase = sptr(smx);
    char* Bsm = smx + A_SM_BYTES;

    // ---- stage A once (cp.async) ----
    {
        const __nv_bfloat16* src = g_acat + ((size_t)g * ROWS + mt * 128) * KC;
        for (int c = tid; c < 128 * 48; c += 256) {
            int row = c / 48, kc = c % 48;
            cpa16(Abase + row * (APAD * 2) + kc * 16, src + (size_t)row * KC + kc * 8);
        }
    }
    cpcommit();

    // B staging geometry: thread -> (batch brow, k-chunk of 16)
    const int brow = tid >> 3;          // 0..31
    const int k0   = (tid & 7) * 16;    // 0..112
    const float* xrow = x + ((size_t)brow * TT + tb * 32) * 1024 + g * 128 + k0;
    char* bdst_row = Bsm + brow * (APAD * 2) + k0 * 2;

    // ---- stage B(0): LDG fp32 -> convert -> STS ----
    {
        float vs[16];
#pragma unroll
        for (int i = 0; i < 4; i++)
            *(float4*)(vs + 4 * i) = *(const float4*)(xrow + 4 * i);
        uint32_t hiw[8], low[8];
#pragma unroll
        for (int i = 0; i < 8; i++) {
            float v0 = vs[2 * i], v1 = vs[2 * i + 1];
            hiw[i] = pkbf(v0, v1);
            float h0 = __bfloat162float(__float2bfloat16(v0));
            float h1 = __bfloat162float(__float2bfloat16(v1));
            low[i] = pkbf(v0 - h0, v1 - h1);
        }
        *(uint4*)(bdst_row)            = make_uint4(hiw[0], hiw[1], hiw[2], hiw[3]);
        *(uint4*)(bdst_row + 16)       = make_uint4(hiw[4], hiw[5], hiw[6], hiw[7]);
        *(uint4*)(bdst_row + 256)      = make_uint4(low[0], low[1], low[2], low[3]);
        *(uint4*)(bdst_row + 256 + 16) = make_uint4(low[4], low[5], low[6], low[7]);
        *(uint4*)(bdst_row + 512)      = make_uint4(hiw[0], hiw[1], hiw[2], hiw[3]);
        *(uint4*)(bdst_row + 512 + 16) = make_uint4(hiw[4], hiw[5], hiw[6], hiw[7]);
    }
    cpwait0();          // A complete

    // lane-invariant ldmatrix offsets
    const uint32_t Bbase = sptr(Bsm);
    const uint32_t aoffs = (uint32_t)(wm * 32 + (lane & 15)) * (APAD * 2) + ((lane >> 4) << 3) * 2;
    const uint32_t boffs = (uint32_t)(wn * 16 + ((lane >> 4) << 3) + (lane & 7)) * (APAD * 2)
                         + (((lane >> 3) & 1) << 3) * 2;

    const int gid = lane >> 2;
    const int tg  = lane & 3;

    const int ob = mt * 128 + wm * 32 + gid;
    float bias[2][2];
    bias[0][0] = b_ih[g * ROWS + ob];
    bias[0][1] = b_ih[g * ROWS + ob + 8];
    bias[1][0] = b_ih[g * ROWS + ob + 16];
    bias[1][1] = b_ih[g * ROWS + ob + 24];

    float* gout = g_gx + ((size_t)(tb * 32) * GR + g) * ROWS * BATCH
                + (size_t)(mt * 128 + wm * 32 + gid) * BATCH + wn * 16 + tg * 2;
    const size_t gstep = (size_t)GR * ROWS * BATCH;

    for (int t = 0; t < 32; t++) {
        // issue x(t+1) loads early (latency covered by MMA loop below)
        float vs[16];
        if (t < 31) {
#pragma unroll
            for (int i = 0; i < 4; i++)
                *(float4*)(vs + 4 * i) = *(const float4*)(xrow + (size_t)(t + 1) * 1024 + 4 * i);
        }

        __syncthreads();    // B(t) STS (prev iter) visible; MMA(t-1) reads done

        const uint32_t Bt = Bbase + (t & 1) * B_SM_BYTES;

        float d[2][2][4];
#pragma unroll
        for (int i = 0; i < 2; i++)
#pragma unroll
            for (int jn = 0; jn < 2; jn++)
#pragma unroll
                for (int e = 0; e < 4; e++) d[i][jn][e] = 0.f;

#pragma unroll
        for (int ks = 0; ks < 24; ks++) {
            const uint32_t kk = ks * 32;
            uint32_t a0[4], a1[4], bb[4];
            ldm4(a0, Abase + aoffs + kk);
            ldm4(a1, Abase + aoffs + 16 * (APAD * 2) + kk);
            ldm4(bb, Bt + boffs + kk);
            mma16816(d[0][0], a0, bb);
            mma16816(d[0][1], a0, bb + 2);
            mma16816(d[1][0], a1, bb);
            mma16816(d[1][1], a1, bb + 2);
        }

        // convert + STS x(t+1) into buffer (t+1)&1
        if (t < 31) {
            uint32_t hiw[8], low[8];
#pragma unroll
            for (int i = 0; i < 8; i++) {
                float v0 = vs[2 * i], v1 = vs[2 * i + 1];
                hiw[i] = pkbf(v0, v1);
                float h0 = __bfloat162float(__float2bfloat16(v0));
                float h1 = __bfloat162float(__float2bfloat16(v1));
                low[i] = pkbf(v0 - h0, v1 - h1);
            }
            char* bd = bdst_row + ((t + 1) & 1) * B_SM_BYTES;
            *(uint4*)(bd)            = make_uint4(hiw[0], hiw[1], hiw[2], hiw[3]);
            *(uint4*)(bd + 16)       = make_uint4(hiw[4], hiw[5], hiw[6], hiw[7]);
            *(uint4*)(bd + 256)      = make_uint4(low[0], low[1], low[2], low[3]);
            *(uint4*)(bd + 256 + 16) = make_uint4(low[4], low[5], low[6], low[7]);
            *(uint4*)(bd + 512)      = make_uint4(hiw[0], hiw[1], hiw[2], hiw[3]);
            *(uint4*)(bd + 512 + 16) = make_uint4(hiw[4], hiw[5], hiw[6], hiw[7]);
        }

        // epilogue: write gx[t][g][o][b] + bias
        float* op = gout + (size_t)t * gstep;
#pragma unroll
        for (int i = 0; i < 2; i++) {
#pragma unroll
            for (int jn = 0; jn < 2; jn++) {
                float2 v0 = make_float2(d[i][jn][0] + bias[i][0], d[i][jn][1] + bias[i][0]);
                float2 v1 = make_float2(d[i][jn][2] + bias[i][1], d[i][jn][3] + bias[i][1]);
                *(float2*)(op + (size_t)(i * 16) * BATCH + jn * 8)     = v0;
                *(float2*)(op + (size_t)(i * 16 + 8) * BATCH + jn * 8) = v1;
            }
        }
    }
}

// ============================================================================
// Phase 2: recurrence — R4 VERBATIM (best: ~600-650us).
// ============================================================================
__global__ void __launch_bounds__(512, 1)
gru_kernel(const float* __restrict__ state,
           const float* __restrict__ W_hh,
           const float* __restrict__ b_hh,
           float* __restrict__ out)
{
    __shared__ __align__(16) float Hb0[2][144];
    __shared__ __align__(16) float Hb1[2][144];
    __shared__ __align__(16) float Gs[3][ROWS * 2];

    const int g   = blockIdx.x >> 4;
    const int bp  = blockIdx.x & 15;
    const int tid = threadIdx.x;
    const int j   = tid >> 2;
    const int q   = tid & 3;
    const int b0  = bp * 2;

    ull wr[16], wz[16], wn[16];
    {
        const float* base = W_hh + (size_t)g * ROWS * 128 + q * 32;
        const float* pr = base + (size_t)(j)       * 128;
        const float* pz = base + (size_t)(128 + j) * 128;
        const float* pn = base + (size_t)(256 + j) * 128;
#pragma unroll
        for (int i = 0; i < 8; i++) {
            ulonglong2 a = *(const ulonglong2*)(pr + i * 4);
            wr[2 * i] = a.x; wr[2 * i + 1] = a.y;
            ulonglong2 b = *(const ulonglong2*)(pz + i * 4);
            wz[2 * i] = b.x; wz[2 * i + 1] = b.y;
            ulonglong2 c = *(const ulonglong2*)(pn + i * 4);
            wn[2 * i] = c.x; wn[2 * i + 1] = c.y;
        }
    }

    const float bhr = b_hh[g * ROWS + j];
    const float bhz = b_hh[g * ROWS + 128 + j];
    const float bhn = b_hh[g * ROWS + 256 + j];

    const int jsw = (j >> 5) * 36 + (j & 31);

    if (q == 0) Hb0[0][jsw] = state[((size_t)g * 32 + b0) * 128 + j];
    if (q == 1) Hb1[0][jsw] = state[((size_t)g * 32 + b0 + 1) * 128 + j];

    const size_t stride_t = (size_t)GR * ROWS * BATCH;
    const float* gx0 = g_gx + (size_t)g * ROWS * BATCH + b0;

    const float* gxt = gx0 + (size_t)tid * BATCH;
    if (tid < ROWS) cpa8(sptr(&Gs[0][tid * 2]), gxt);
    cpcommit();
    if (tid < ROWS) cpa8(sptr(&Gs[1][tid * 2]), gxt + stride_t);
    cpcommit();
    gxt += 2 * stride_t;
    cpwait1();
    __syncthreads();

    const int myb = q >> 1;
    float* outp = out + ((size_t)(b0 + myb) * TT) * 1024 + g * 128 + j;

    const int qoff = q * 36;
    int p = 0, cb = 0;

    for (int t = 0; t < TT; t++) {
        {
            int nb = cb + 2; if (nb >= 3) nb -= 3;
            if (t + 2 < TT && tid < ROWS)
                cpa8(sptr(&Gs[nb][tid * 2]), gxt);
            cpcommit();
            gxt += stride_t;
        }

        const float* H0 = Hb0[p];
        const float* H1 = Hb1[p];

        ull ar0 = 0, az0 = 0, an0 = 0;
        ull ar1 = 0, az1 = 0, an1 = 0;

#pragma unroll
        for (int i = 0; i < 8; i++) {
            ulonglong2 h0 = *(const ulonglong2*)(H0 + qoff + i * 4);
            ulonglong2 h1 = *(const ulonglong2*)(H1 + qoff + i * 4);
            fma2(ar0, wr[2 * i],     h0.x);
            fma2(az0, wz[2 * i],     h0.x);
            fma2(an0, wn[2 * i],     h0.x);
            fma2(ar1, wr[2 * i],     h1.x);
            fma2(az1, wz[2 * i],     h1.x);
            fma2(an1, wn[2 * i],     h1.x);
            fma2(ar0, wr[2 * i + 1], h0.y);
            fma2(az0, wz[2 * i + 1], h0.y);
            fma2(an0, wn[2 * i + 1], h0.y);
            fma2(ar1, wr[2 * i + 1], h1.y);
            fma2(az1, wz[2 * i + 1], h1.y);
            fma2(an1, wn[2 * i + 1], h1.y);
        }

        float sr0 = hadd(ar0), sz0 = hadd(az0), sn0 = hadd(an0);
        float sr1 = hadd(ar1), sz1 = hadd(az1), sn1 = hadd(an1);

        const bool hi = (q & 2) != 0;
        float vr = hi ? sr0 : sr1;
        float vz = hi ? sz0 : sz1;
        float vn = hi ? sn0 : sn1;
        float kr = hi ? sr1 : sr0;
        float kz = hi ? sz1 : sz0;
        float kn = hi ? sn1 : sn0;
        kr += __shfl_xor_sync(0xffffffffu, vr, 2);
        kz += __shfl_xor_sync(0xffffffffu, vz, 2);
        kn += __shfl_xor_sync(0xffffffffu, vn, 2);
        kr += __shfl_xor_sync(0xffffffffu, kr, 1);
        kz += __shfl_xor_sync(0xffffffffu, kz, 1);
        kn += __shfl_xor_sync(0xffffffffu, kn, 1);

        const float* Gc = Gs[cb];
        float gr_ = Gc[(j)       * 2 + myb];
        float gz_ = Gc[(128 + j) * 2 + myb];
        float gn_ = Gc[(256 + j) * 2 + myb];
        float hold = (hi ? H1 : H0)[jsw];

        float rr = sigm(gr_ + kr + bhr);
        float zz = sigm(gz_ + kz + bhz);
        float nn = tanh_(gn_ + rr * (kn + bhn));
        float hn = nn + zz * (hold - nn);

        const int np = p ^ 1;
        if (q == 0) {
            Hb0[np][jsw] = hn;
        } else if (q == 2) {
            Hb1[np][jsw] = hn;
        } else {
            *outp = hn;
        }
        outp += 1024;

        cpwait1();
        __syncthreads();
        p = np;
        cb = cb + 1; if (cb >= 3) cb -= 3;
    }

    float* hop = out + (size_t)BATCH * TT * 1024;
    if (q == 0) hop[((size_t)g * 32 + b0) * 128 + j]     = Hb0[p][jsw];
    if (q == 2) hop[((size_t)g * 32 + b0 + 1) * 128 + j] = Hb1[p][jsw];
}

extern "C" void kernel_launch(void* const* d_in, const int* in_sizes, int n_in,
                              void* d_out, int out_size)
{
    const float* x     = (const float*)d_in[0];
    const float* state = (const float*)d_in[1];
    const float* W_ih  = (const float*)d_in[2];
    const float* W_hh  = (const float*)d_in[3];
    const float* b_ih  = (const float*)d_in[4];
    const float* b_hh  = (const float*)d_in[5];
    float* out = (float*)d_out;

    const int smem_mma = A_SM_BYTES + 2 * B_SM_BYTES;   // 150,528
    cudaFuncSetAttribute(gx_mma, cudaFuncAttributeMaxDynamicSharedMemorySize, smem_mma);

    prep_w<<<1536, 256>>>(W_ih);
    gx_mma<<<384, 256, smem_mma>>>(x, b_ih);
    gru_kernel<<<128, 512>>>(state, W_hh, b_hh, out);
}

// round 12
// speedup vs baseline: 2.3959x; 1.0305x over previous
#include <cuda_runtime.h>
#include <cuda_bf16.h>
#include <cstdint>

#define GR 8
#define BATCH 32
#define TT 512
#define ROWS 384          // 3 * 128
#define KC 384            // cat-K
#define APAD 392          // smem row stride (bf16)

typedef unsigned long long ull;

// scratch: gx fp32 (201MB), split-bf16 A operand
__device__ float g_gx[(size_t)TT * GR * ROWS * BATCH];
__device__ __nv_bfloat16 g_acat[(size_t)GR * ROWS * KC];         // [g][o][k]

__device__ __forceinline__ ull pk(float lo, float hi) {
    ull r;
    asm("mov.b64 %0, {%1, %2};" : "=l"(r) : "f"(lo), "f"(hi));
    return r;
}
__device__ __forceinline__ float2 up(ull v) {
    float2 r;
    asm("mov.b64 {%0, %1}, %2;" : "=f"(r.x), "=f"(r.y) : "l"(v));
    return r;
}
__device__ __forceinline__ void fma2(ull& d, ull a, ull b) {
    asm("fma.rn.f32x2 %0, %1, %2, %0;" : "+l"(d) : "l"(a), "l"(b));
}
__device__ __forceinline__ float sigm(float x) {
    return __fdividef(1.0f, 1.0f + __expf(-x));
}
__device__ __forceinline__ float tanh_(float x) {
    return 1.0f - __fdividef(2.0f, __expf(2.0f * x) + 1.0f);
}
__device__ __forceinline__ float hadd(ull v) {
    float2 u = up(v);
    return u.x + u.y;
}
__device__ __forceinline__ unsigned sptr(const void* p) {
    return (unsigned)__cvta_generic_to_shared(p);
}
__device__ __forceinline__ void cpa8(unsigned d, const void* s) {
    asm volatile("cp.async.ca.shared.global [%0], [%1], 8;" :: "r"(d), "l"(s));
}
__device__ __forceinline__ void cpa16(unsigned d, const void* s) {
    asm volatile("cp.async.cg.shared.global [%0], [%1], 16;" :: "r"(d), "l"(s));
}
__device__ __forceinline__ void cpcommit() { asm volatile("cp.async.commit_group;" ::: "memory"); }
__device__ __forceinline__ void cpwait0()  { asm volatile("cp.async.wait_group 0;" ::: "memory"); }
__device__ __forceinline__ void cpwait1()  { asm volatile("cp.async.wait_group 1;" ::: "memory"); }

__device__ __forceinline__ void ldm4(uint32_t* r, unsigned addr) {
    asm volatile("ldmatrix.sync.aligned.m8n8.x4.shared.b16 {%0,%1,%2,%3}, [%4];"
                 : "=r"(r[0]), "=r"(r[1]), "=r"(r[2]), "=r"(r[3]) : "r"(addr));
}
__device__ __forceinline__ void mma16816(float* d, const uint32_t* a, const uint32_t* b) {
    asm volatile(
        "mma.sync.aligned.m16n8k16.row.col.f32.bf16.bf16.f32 "
        "{%0,%1,%2,%3}, {%4,%5,%6,%7}, {%8,%9}, {%0,%1,%2,%3};"
        : "+f"(d[0]), "+f"(d[1]), "+f"(d[2]), "+f"(d[3])
        : "r"(a[0]), "r"(a[1]), "r"(a[2]), "r"(a[3]), "r"(b[0]), "r"(b[1]));
}
__device__ __forceinline__ uint32_t pkbf(float v0, float v1) {
    __nv_bfloat16 b0 = __float2bfloat16(v0);
    __nv_bfloat16 b1 = __float2bfloat16(v1);
    return (uint32_t)__bfloat16_as_ushort(b0) | ((uint32_t)__bfloat16_as_ushort(b1) << 16);
}

// ============================================================================
// prep_w: A_cat[g][o] = [bf16(W) | bf16(W) | Wlo] over k
// ============================================================================
__global__ void prep_w(const float* __restrict__ W_ih)
{
    int idx = blockIdx.x * 256 + threadIdx.x;
    if (idx >= GR * ROWS * 128) return;
    float v = W_ih[idx];
    int k = idx & 127;
    int go = idx >> 7;
    __nv_bfloat16 hi = __float2bfloat16(v);
    __nv_bfloat16 lo = __float2bfloat16(v - __bfloat162float(hi));
    __nv_bfloat16* dst = g_acat + (size_t)go * KC;
    dst[k] = hi; dst[128 + k] = hi; dst[256 + k] = lo;
}

// ============================================================================
// gx_mma v2: CTA (g, mt, tb): 16 passes, each computing TWO timesteps:
// D[128 x 64] = A[128 x 384] * B[64 x 384]^T, where B row r = tloc*32 + b
// (tloc = timestep within pair). Warp grid 4(m) x 2(n); warp-n == tloc, so
// each warp's epilogue writes exactly one timestep. A-ldmatrix amortized
// over 2 t: crossbar 2304 -> 1536 wf/t. B double-buffered, conversion from
// registers (LDG issued before the mma loop). 1 barrier per pass.
// ============================================================================
#define A_SM_BYTES (128 * APAD * 2)      // 100,352
#define B_SM_BYTES (64 * APAD * 2)       // 50,176

__global__ void __launch_bounds__(256, 1)
gx_mma(const float* __restrict__ x, const float* __restrict__ b_ih)
{
    extern __shared__ __align__(1024) char smx[];      // A | B0 | B1
    const int bx  = blockIdx.x;                        // 8g * 48
    const int g   = bx & 7;
    const int r   = bx >> 3;
    const int mt  = r % 3;
    const int tb  = r / 3;
    const int tid = threadIdx.x;
    const int wid = tid >> 5;
    const int lane = tid & 31;
    const int wm  = wid >> 1;           // 0..3 (m)
    const int wn  = wid & 1;            // 0..1 (n == tloc)

    const uint32_t Abase = sptr(smx);
    char* Bsm = smx + A_SM_BYTES;

    // ---- stage A once (cp.async) ----
    {
        const __nv_bfloat16* src = g_acat + ((size_t)g * ROWS + mt * 128) * KC;
        for (int c = tid; c < 128 * 48; c += 256) {
            int row = c / 48, kc = c % 48;
            cpa16(Abase + row * (APAD * 2) + kc * 16, src + (size_t)row * KC + kc * 8);
        }
    }
    cpcommit();

    // staging geometry: thread -> (batch brow, 16-float k-chunk), BOTH tlocs
    const int brow = tid >> 3;          // 0..31
    const int k0   = (tid & 7) * 16;    // 0..112
    const float* xrow = x + ((size_t)brow * TT + tb * 32) * 1024 + g * 128 + k0;

    // convert 16 floats -> one cat row [hi|lo|hi] at dst
    auto cvt_store = [&](const float* v, char* dst) {
        uint32_t hiw[8], low[8];
#pragma unroll
        for (int i = 0; i < 8; i++) {
            float v0 = v[2 * i], v1 = v[2 * i + 1];
            hiw[i] = pkbf(v0, v1);
            float h0 = __bfloat162float(__float2bfloat16(v0));
            float h1 = __bfloat162float(__float2bfloat16(v1));
            low[i] = pkbf(v0 - h0, v1 - h1);
        }
        *(uint4*)(dst)            = make_uint4(hiw[0], hiw[1], hiw[2], hiw[3]);
        *(uint4*)(dst + 16)       = make_uint4(hiw[4], hiw[5], hiw[6], hiw[7]);
        *(uint4*)(dst + 256)      = make_uint4(low[0], low[1], low[2], low[3]);
        *(uint4*)(dst + 256 + 16) = make_uint4(low[4], low[5], low[6], low[7]);
        *(uint4*)(dst + 512)      = make_uint4(hiw[0], hiw[1], hiw[2], hiw[3]);
        *(uint4*)(dst + 512 + 16) = make_uint4(hiw[4], hiw[5], hiw[6], hiw[7]);
    };
    const int dst_off0 = brow * (APAD * 2) + k0 * 2;          // row tloc=0
    const int dst_off1 = (32 + brow) * (APAD * 2) + k0 * 2;   // row tloc=1

    // ---- prologue: load + convert pass 0 into B0 ----
    {
        float vs[32];
#pragma unroll
        for (int i = 0; i < 4; i++) {
            *(float4*)(vs + 4 * i)      = *(const float4*)(xrow + 4 * i);
            *(float4*)(vs + 16 + 4 * i) = *(const float4*)(xrow + 1024 + 4 * i);
        }
        cvt_store(vs,      Bsm + dst_off0);
        cvt_store(vs + 16, Bsm + dst_off1);
    }
    cpwait0();          // A complete
    __syncthreads();

    // lane-invariant ldmatrix offsets
    const uint32_t Bbase = sptr(Bsm);
    const uint32_t aoffs = (uint32_t)(wm * 32 + (lane & 15)) * (APAD * 2) + ((lane >> 4) << 3) * 2;
    const uint32_t boffs = (uint32_t)(wn * 32 + ((lane >> 4) << 3) + (lane & 7)) * (APAD * 2)
                         + (((lane >> 3) & 1) << 3) * 2;

    const int gid = lane >> 2;
    const int tg  = lane & 3;

    const int ob = mt * 128 + wm * 32 + gid;
    float bias[2][2];
    bias[0][0] = b_ih[g * ROWS + ob];
    bias[0][1] = b_ih[g * ROWS + ob + 8];
    bias[1][0] = b_ih[g * ROWS + ob + 16];
    bias[1][1] = b_ih[g * ROWS + ob + 24];

    // warp wn owns timestep (tb*32 + p*2 + wn); columns = batches nt*8+tg*2
    float* gout = g_gx + ((size_t)(tb * 32 + wn) * GR + g) * ROWS * BATCH
                + (size_t)(mt * 128 + wm * 32 + gid) * BATCH + tg * 2;
    const size_t gstep = (size_t)GR * ROWS * BATCH;

    for (int p = 0; p < 16; p++) {
        // load x for pass p+1 early (latency covered by mma loop)
        float vs[32];
        if (p < 15) {
            const float* xp = xrow + (size_t)((p + 1) * 2) * 1024;
#pragma unroll
            for (int i = 0; i < 4; i++) {
                *(float4*)(vs + 4 * i)      = *(const float4*)(xp + 4 * i);
                *(float4*)(vs + 16 + 4 * i) = *(const float4*)(xp + 1024 + 4 * i);
            }
        }

        const uint32_t Bt = Bbase + (p & 1) * B_SM_BYTES;

        float d[2][4][4];
#pragma unroll
        for (int i = 0; i < 2; i++)
#pragma unroll
            for (int nt = 0; nt < 4; nt++)
#pragma unroll
                for (int e = 0; e < 4; e++) d[i][nt][e] = 0.f;

#pragma unroll
        for (int ks = 0; ks < 24; ks++) {
            const uint32_t kk = ks * 32;
            uint32_t a0[4], a1[4], bA[4], bB[4];
            ldm4(a0, Abase + aoffs + kk);
            ldm4(a1, Abase + aoffs + 16 * (APAD * 2) + kk);
            ldm4(bA, Bt + boffs + kk);
            ldm4(bB, Bt + boffs + 16 * (APAD * 2) + kk);
            mma16816(d[0][0], a0, bA);
            mma16816(d[0][1], a0, bA + 2);
            mma16816(d[0][2], a0, bB);
            mma16816(d[0][3], a0, bB + 2);
            mma16816(d[1][0], a1, bA);
            mma16816(d[1][1], a1, bA + 2);
            mma16816(d[1][2], a1, bB);
            mma16816(d[1][3], a1, bB + 2);
        }

        // convert + STS pass p+1 into the other buffer
        if (p < 15) {
            char* bd = Bsm + ((p + 1) & 1) * B_SM_BYTES;
            cvt_store(vs,      bd + dst_off0);
            cvt_store(vs + 16, bd + dst_off1);
        }

        // epilogue: timestep tb*32 + p*2 + wn
        float* op = gout + (size_t)(p * 2) * gstep;
#pragma unroll
        for (int i = 0; i < 2; i++) {
#pragma unroll
            for (int nt = 0; nt < 4; nt++) {
                float2 v0 = make_float2(d[i][nt][0] + bias[i][0], d[i][nt][1] + bias[i][0]);
                float2 v1 = make_float2(d[i][nt][2] + bias[i][1], d[i][nt][3] + bias[i][1]);
                *(float2*)(op + (size_t)(i * 16) * BATCH + nt * 8)     = v0;
                *(float2*)(op + (size_t)(i * 16 + 8) * BATCH + nt * 8) = v1;
            }
        }
        __syncthreads();    // mma reads of B[p] done; B[p+1] STS visible
    }
}

// ============================================================================
// Phase 2: recurrence — R4 VERBATIM (best: ~600us).
// ============================================================================
__global__ void __launch_bounds__(512, 1)
gru_kernel(const float* __restrict__ state,
           const float* __restrict__ W_hh,
           const float* __restrict__ b_hh,
           float* __restrict__ out)
{
    __shared__ __align__(16) float Hb0[2][144];
    __shared__ __align__(16) float Hb1[2][144];
    __shared__ __align__(16) float Gs[3][ROWS * 2];

    const int g   = blockIdx.x >> 4;
    const int bp  = blockIdx.x & 15;
    const int tid = threadIdx.x;
    const int j   = tid >> 2;
    const int q   = tid & 3;
    const int b0  = bp * 2;

    ull wr[16], wz[16], wn[16];
    {
        const float* base = W_hh + (size_t)g * ROWS * 128 + q * 32;
        const float* pr = base + (size_t)(j)       * 128;
        const float* pz = base + (size_t)(128 + j) * 128;
        const float* pn = base + (size_t)(256 + j) * 128;
#pragma unroll
        for (int i = 0; i < 8; i++) {
            ulonglong2 a = *(const ulonglong2*)(pr + i * 4);
            wr[2 * i] = a.x; wr[2 * i + 1] = a.y;
            ulonglong2 b = *(const ulonglong2*)(pz + i * 4);
            wz[2 * i] = b.x; wz[2 * i + 1] = b.y;
            ulonglong2 c = *(const ulonglong2*)(pn + i * 4);
            wn[2 * i] = c.x; wn[2 * i + 1] = c.y;
        }
    }

    const float bhr = b_hh[g * ROWS + j];
    const float bhz = b_hh[g * ROWS + 128 + j];
    const float bhn = b_hh[g * ROWS + 256 + j];

    const int jsw = (j >> 5) * 36 + (j & 31);

    if (q == 0) Hb0[0][jsw] = state[((size_t)g * 32 + b0) * 128 + j];
    if (q == 1) Hb1[0][jsw] = state[((size_t)g * 32 + b0 + 1) * 128 + j];

    const size_t stride_t = (size_t)GR * ROWS * BATCH;
    const float* gx0 = g_gx + (size_t)g * ROWS * BATCH + b0;

    const float* gxt = gx0 + (size_t)tid * BATCH;
    if (tid < ROWS) cpa8(sptr(&Gs[0][tid * 2]), gxt);
    cpcommit();
    if (tid < ROWS) cpa8(sptr(&Gs[1][tid * 2]), gxt + stride_t);
    cpcommit();
    gxt += 2 * stride_t;
    cpwait1();
    __syncthreads();

    const int myb = q >> 1;
    float* outp = out + ((size_t)(b0 + myb) * TT) * 1024 + g * 128 + j;

    const int qoff = q * 36;
    int p = 0, cb = 0;

    for (int t = 0; t < TT; t++) {
        {
            int nb = cb + 2; if (nb >= 3) nb -= 3;
            if (t + 2 < TT && tid < ROWS)
                cpa8(sptr(&Gs[nb][tid * 2]), gxt);
            cpcommit();
            gxt += stride_t;
        }

        const float* H0 = Hb0[p];
        const float* H1 = Hb1[p];

        ull ar0 = 0, az0 = 0, an0 = 0;
        ull ar1 = 0, az1 = 0, an1 = 0;

#pragma unroll
        for (int i = 0; i < 8; i++) {
            ulonglong2 h0 = *(const ulonglong2*)(H0 + qoff + i * 4);
            ulonglong2 h1 = *(const ulonglong2*)(H1 + qoff + i * 4);
            fma2(ar0, wr[2 * i],     h0.x);
            fma2(az0, wz[2 * i],     h0.x);
            fma2(an0, wn[2 * i],     h0.x);
            fma2(ar1, wr[2 * i],     h1.x);
            fma2(az1, wz[2 * i],     h1.x);
            fma2(an1, wn[2 * i],     h1.x);
            fma2(ar0, wr[2 * i + 1], h0.y);
            fma2(az0, wz[2 * i + 1], h0.y);
            fma2(an0, wn[2 * i + 1], h0.y);
            fma2(ar1, wr[2 * i + 1], h1.y);
            fma2(az1, wz[2 * i + 1], h1.y);
            fma2(an1, wn[2 * i + 1], h1.y);
        }

        float sr0 = hadd(ar0), sz0 = hadd(az0), sn0 = hadd(an0);
        float sr1 = hadd(ar1), sz1 = hadd(az1), sn1 = hadd(an1);

        const bool hi = (q & 2) != 0;
        float vr = hi ? sr0 : sr1;
        float vz = hi ? sz0 : sz1;
        float vn = hi ? sn0 : sn1;
        float kr = hi ? sr1 : sr0;
        float kz = hi ? sz1 : sz0;
        float kn = hi ? sn1 : sn0;
        kr += __shfl_xor_sync(0xffffffffu, vr, 2);
        kz += __shfl_xor_sync(0xffffffffu, vz, 2);
        kn += __shfl_xor_sync(0xffffffffu, vn, 2);
        kr += __shfl_xor_sync(0xffffffffu, kr, 1);
        kz += __shfl_xor_sync(0xffffffffu, kz, 1);
        kn += __shfl_xor_sync(0xffffffffu, kn, 1);

        const float* Gc = Gs[cb];
        float gr_ = Gc[(j)       * 2 + myb];
        float gz_ = Gc[(128 + j) * 2 + myb];
        float gn_ = Gc[(256 + j) * 2 + myb];
        float hold = (hi ? H1 : H0)[jsw];

        float rr = sigm(gr_ + kr + bhr);
        float zz = sigm(gz_ + kz + bhz);
        float nn = tanh_(gn_ + rr * (kn + bhn));
        float hn = nn + zz * (hold - nn);

        const int np = p ^ 1;
        if (q == 0) {
            Hb0[np][jsw] = hn;
        } else if (q == 2) {
            Hb1[np][jsw] = hn;
        } else {
            *outp = hn;
        }
        outp += 1024;

        cpwait1();
        __syncthreads();
        p = np;
        cb = cb + 1; if (cb >= 3) cb -= 3;
    }

    float* hop = out + (size_t)BATCH * TT * 1024;
    if (q == 0) hop[((size_t)g * 32 + b0) * 128 + j]     = Hb0[p][jsw];
    if (q == 2) hop[((size_t)g * 32 + b0 + 1) * 128 + j] = Hb1[p][jsw];
}

extern "C" void kernel_launch(void* const* d_in, const int* in_sizes, int n_in,
                              void* d_out, int out_size)
{
    const float* x     = (const float*)d_in[0];
    const float* state = (const float*)d_in[1];
    const float* W_ih  = (const float*)d_in[2];
    const float* W_hh  = (const float*)d_in[3];
    const float* b_ih  = (const float*)d_in[4];
    const float* b_hh  = (const float*)d_in[5];
    float* out = (float*)d_out;

    const int smem_mma = A_SM_BYTES + 2 * B_SM_BYTES;   // 200,704
    cudaFuncSetAttribute(gx_mma, cudaFuncAttributeMaxDynamicSharedMemorySize, smem_mma);

    prep_w<<<1536, 256>>>(W_ih);
    gx_mma<<<384, 256, smem_mma>>>(x, b_ih);
    gru_kernel<<<128, 512>>>(state, W_hh, b_hh, out);
}

// round 13
// speedup vs baseline: 2.3992x; 1.0014x over previous
#include <cuda_runtime.h>
#include <cuda_bf16.h>
#include <cstdint>

#define GR 8
#define BATCH 32
#define TT 512
#define ROWS 384          // 3 * 128
#define KC 384            // cat-K
#define APAD 392          // smem row stride (bf16)

typedef unsigned long long ull;

// scratch: gx fp32 (201MB), split-bf16 A operand
__device__ float g_gx[(size_t)TT * GR * ROWS * BATCH];
__device__ __nv_bfloat16 g_acat[(size_t)GR * ROWS * KC];         // [g][o][k]

__device__ __forceinline__ ull pk(float lo, float hi) {
    ull r;
    asm("mov.b64 %0, {%1, %2};" : "=l"(r) : "f"(lo), "f"(hi));
    return r;
}
__device__ __forceinline__ float2 up(ull v) {
    float2 r;
    asm("mov.b64 {%0, %1}, %2;" : "=f"(r.x), "=f"(r.y) : "l"(v));
    return r;
}
__device__ __forceinline__ void fma2(ull& d, ull a, ull b) {
    asm("fma.rn.f32x2 %0, %1, %2, %0;" : "+l"(d) : "l"(a), "l"(b));
}
__device__ __forceinline__ float sigm(float x) {
    return __fdividef(1.0f, 1.0f + __expf(-x));
}
__device__ __forceinline__ float tanh_(float x) {
    return 1.0f - __fdividef(2.0f, __expf(2.0f * x) + 1.0f);
}
__device__ __forceinline__ float hadd(ull v) {
    float2 u = up(v);
    return u.x + u.y;
}
__device__ __forceinline__ unsigned sptr(const void* p) {
    return (unsigned)__cvta_generic_to_shared(p);
}
__device__ __forceinline__ void cpa8(unsigned d, const void* s) {
    asm volatile("cp.async.ca.shared.global [%0], [%1], 8;" :: "r"(d), "l"(s));
}
__device__ __forceinline__ void cpa16(unsigned d, const void* s) {
    asm volatile("cp.async.cg.shared.global [%0], [%1], 16;" :: "r"(d), "l"(s));
}
__device__ __forceinline__ void cpcommit() { asm volatile("cp.async.commit_group;" ::: "memory"); }
__device__ __forceinline__ void cpwait0()  { asm volatile("cp.async.wait_group 0;" ::: "memory"); }
__device__ __forceinline__ void cpwait1()  { asm volatile("cp.async.wait_group 1;" ::: "memory"); }

__device__ __forceinline__ void ldm4(uint32_t* r, unsigned addr) {
    asm volatile("ldmatrix.sync.aligned.m8n8.x4.shared.b16 {%0,%1,%2,%3}, [%4];"
                 : "=r"(r[0]), "=r"(r[1]), "=r"(r[2]), "=r"(r[3]) : "r"(addr));
}
__device__ __forceinline__ void mma16816(float* d, const uint32_t* a, const uint32_t* b) {
    asm volatile(
        "mma.sync.aligned.m16n8k16.row.col.f32.bf16.bf16.f32 "
        "{%0,%1,%2,%3}, {%4,%5,%6,%7}, {%8,%9}, {%0,%1,%2,%3};"
        : "+f"(d[0]), "+f"(d[1]), "+f"(d[2]), "+f"(d[3])
        : "r"(a[0]), "r"(a[1]), "r"(a[2]), "r"(a[3]), "r"(b[0]), "r"(b[1]));
}
__device__ __forceinline__ uint32_t pkbf(float v0, float v1) {
    __nv_bfloat16 b0 = __float2bfloat16(v0);
    __nv_bfloat16 b1 = __float2bfloat16(v1);
    return (uint32_t)__bfloat16_as_ushort(b0) | ((uint32_t)__bfloat16_as_ushort(b1) << 16);
}

// ============================================================================
// prep_w: A_cat[g][o] = [bf16(W) | bf16(W) | Wlo] over k
// ============================================================================
__global__ void prep_w(const float* __restrict__ W_ih)
{
    int idx = blockIdx.x * 256 + threadIdx.x;
    if (idx >= GR * ROWS * 128) return;
    float v = W_ih[idx];
    int k = idx & 127;
    int go = idx >> 7;
    __nv_bfloat16 hi = __float2bfloat16(v);
    __nv_bfloat16 lo = __float2bfloat16(v - __bfloat162float(hi));
    __nv_bfloat16* dst = g_acat + (size_t)go * KC;
    dst[k] = hi; dst[128 + k] = hi; dst[256 + k] = lo;
}

// ============================================================================
// gx_mma v3: R12 (2 timesteps per pass, N=64) + A-FRAGMENT REGISTER CACHING:
// A fragments for k-steps 0..11 loaded once into registers (96 regs; 256-thr
// cap is 255, big slack) -> per-pass ldmatrix drops 96 -> 72, crossbar
// 192 -> 144 wf/t, and those loads leave the dependency chain entirely.
// ============================================================================
#define A_SM_BYTES (128 * APAD * 2)      // 100,352
#define B_SM_BYTES (64 * APAD * 2)       // 50,176
#define KS_CACHED 12

__global__ void __launch_bounds__(256, 1)
gx_mma(const float* __restrict__ x, const float* __restrict__ b_ih)
{
    extern __shared__ __align__(1024) char smx[];      // A | B0 | B1
    const int bx  = blockIdx.x;                        // 8g * 48
    const int g   = bx & 7;
    const int r   = bx >> 3;
    const int mt  = r % 3;
    const int tb  = r / 3;
    const int tid = threadIdx.x;
    const int wid = tid >> 5;
    const int lane = tid & 31;
    const int wm  = wid >> 1;           // 0..3 (m)
    const int wn  = wid & 1;            // 0..1 (n == tloc)

    const uint32_t Abase = sptr(smx);
    char* Bsm = smx + A_SM_BYTES;

    // ---- stage A once (cp.async) ----
    {
        const __nv_bfloat16* src = g_acat + ((size_t)g * ROWS + mt * 128) * KC;
        for (int c = tid; c < 128 * 48; c += 256) {
            int row = c / 48, kc = c % 48;
            cpa16(Abase + row * (APAD * 2) + kc * 16, src + (size_t)row * KC + kc * 8);
        }
    }
    cpcommit();

    // staging geometry: thread -> (batch brow, 16-float k-chunk), BOTH tlocs
    const int brow = tid >> 3;          // 0..31
    const int k0   = (tid & 7) * 16;    // 0..112
    const float* xrow = x + ((size_t)brow * TT + tb * 32) * 1024 + g * 128 + k0;

    // convert 16 floats -> one cat row [hi|lo|hi] at dst
    auto cvt_store = [&](const float* v, char* dst) {
        uint32_t hiw[8], low[8];
#pragma unroll
        for (int i = 0; i < 8; i++) {
            float v0 = v[2 * i], v1 = v[2 * i + 1];
            hiw[i] = pkbf(v0, v1);
            float h0 = __bfloat162float(__float2bfloat16(v0));
            float h1 = __bfloat162float(__float2bfloat16(v1));
            low[i] = pkbf(v0 - h0, v1 - h1);
        }
        *(uint4*)(dst)            = make_uint4(hiw[0], hiw[1], hiw[2], hiw[3]);
        *(uint4*)(dst + 16)       = make_uint4(hiw[4], hiw[5], hiw[6], hiw[7]);
        *(uint4*)(dst + 256)      = make_uint4(low[0], low[1], low[2], low[3]);
        *(uint4*)(dst + 256 + 16) = make_uint4(low[4], low[5], low[6], low[7]);
        *(uint4*)(dst + 512)      = make_uint4(hiw[0], hiw[1], hiw[2], hiw[3]);
        *(uint4*)(dst + 512 + 16) = make_uint4(hiw[4], hiw[5], hiw[6], hiw[7]);
    };
    const int dst_off0 = brow * (APAD * 2) + k0 * 2;          // row tloc=0
    const int dst_off1 = (32 + brow) * (APAD * 2) + k0 * 2;   // row tloc=1

    // ---- prologue: load + convert pass 0 into B0 ----
    {
        float vs[32];
#pragma unroll
        for (int i = 0; i < 4; i++) {
            *(float4*)(vs + 4 * i)      = *(const float4*)(xrow + 4 * i);
            *(float4*)(vs + 16 + 4 * i) = *(const float4*)(xrow + 1024 + 4 * i);
        }
        cvt_store(vs,      Bsm + dst_off0);
        cvt_store(vs + 16, Bsm + dst_off1);
    }
    cpwait0();          // A complete
    __syncthreads();

    // lane-invariant ldmatrix offsets
    const uint32_t Bbase = sptr(Bsm);
    const uint32_t aoffs = (uint32_t)(wm * 32 + (lane & 15)) * (APAD * 2) + ((lane >> 4) << 3) * 2;
    const uint32_t boffs = (uint32_t)(wn * 32 + ((lane >> 4) << 3) + (lane & 7)) * (APAD * 2)
                         + (((lane >> 3) & 1) << 3) * 2;

    // ---- cache A fragments for k-steps 0..KS_CACHED-1 in registers ----
    uint32_t Af0[KS_CACHED][4], Af1[KS_CACHED][4];
#pragma unroll
    for (int ks = 0; ks < KS_CACHED; ks++) {
        ldm4(Af0[ks], Abase + aoffs + ks * 32);
        ldm4(Af1[ks], Abase + aoffs + 16 * (APAD * 2) + ks * 32);
    }

    const int gid = lane >> 2;
    const int tg  = lane & 3;

    const int ob = mt * 128 + wm * 32 + gid;
    float bias[2][2];
    bias[0][0] = b_ih[g * ROWS + ob];
    bias[0][1] = b_ih[g * ROWS + ob + 8];
    bias[1][0] = b_ih[g * ROWS + ob + 16];
    bias[1][1] = b_ih[g * ROWS + ob + 24];

    // warp wn owns timestep (tb*32 + p*2 + wn); columns = batches nt*8+tg*2
    float* gout = g_gx + ((size_t)(tb * 32 + wn) * GR + g) * ROWS * BATCH
                + (size_t)(mt * 128 + wm * 32 + gid) * BATCH + tg * 2;
    const size_t gstep = (size_t)GR * ROWS * BATCH;

    for (int p = 0; p < 16; p++) {
        // load x for pass p+1 early (latency covered by mma loop)
        float vs[32];
        if (p < 15) {
            const float* xp = xrow + (size_t)((p + 1) * 2) * 1024;
#pragma unroll
            for (int i = 0; i < 4; i++) {
                *(float4*)(vs + 4 * i)      = *(const float4*)(xp + 4 * i);
                *(float4*)(vs + 16 + 4 * i) = *(const float4*)(xp + 1024 + 4 * i);
            }
        }

        const uint32_t Bt = Bbase + (p & 1) * B_SM_BYTES;

        float d[2][4][4];
#pragma unroll
        for (int i = 0; i < 2; i++)
#pragma unroll
            for (int nt = 0; nt < 4; nt++)
#pragma unroll
                for (int e = 0; e < 4; e++) d[i][nt][e] = 0.f;

#pragma unroll
        for (int ks = 0; ks < 24; ks++) {
            const uint32_t kk = ks * 32;
            uint32_t at0[4], at1[4], bA[4], bB[4];
            const uint32_t* a0;
            const uint32_t* a1;
            if (ks < KS_CACHED) {
                a0 = Af0[ks];
                a1 = Af1[ks];
            } else {
                ldm4(at0, Abase + aoffs + kk);
                ldm4(at1, Abase + aoffs + 16 * (APAD * 2) + kk);
                a0 = at0;
                a1 = at1;
            }
            ldm4(bA, Bt + boffs + kk);
            ldm4(bB, Bt + boffs + 16 * (APAD * 2) + kk);
            mma16816(d[0][0], a0, bA);
            mma16816(d[0][1], a0, bA + 2);
            mma16816(d[0][2], a0, bB);
            mma16816(d[0][3], a0, bB + 2);
            mma16816(d[1][0], a1, bA);
            mma16816(d[1][1], a1, bA + 2);
            mma16816(d[1][2], a1, bB);
            mma16816(d[1][3], a1, bB + 2);
        }

        // convert + STS pass p+1 into the other buffer
        if (p < 15) {
            char* bd = Bsm + ((p + 1) & 1) * B_SM_BYTES;
            cvt_store(vs,      bd + dst_off0);
            cvt_store(vs + 16, bd + dst_off1);
        }

        // epilogue: timestep tb*32 + p*2 + wn
        float* op = gout + (size_t)(p * 2) * gstep;
#pragma unroll
        for (int i = 0; i < 2; i++) {
#pragma unroll
            for (int nt = 0; nt < 4; nt++) {
                float2 v0 = make_float2(d[i][nt][0] + bias[i][0], d[i][nt][1] + bias[i][0]);
                float2 v1 = make_float2(d[i][nt][2] + bias[i][1], d[i][nt][3] + bias[i][1]);
                *(float2*)(op + (size_t)(i * 16) * BATCH + nt * 8)     = v0;
                *(float2*)(op + (size_t)(i * 16 + 8) * BATCH + nt * 8) = v1;
            }
        }
        __syncthreads();    // mma reads of B[p] done; B[p+1] STS visible
    }
}

// ============================================================================
// Phase 2: recurrence — R4 VERBATIM (best: ~600us).
// ============================================================================
__global__ void __launch_bounds__(512, 1)
gru_kernel(const float* __restrict__ state,
           const float* __restrict__ W_hh,
           const float* __restrict__ b_hh,
           float* __restrict__ out)
{
    __shared__ __align__(16) float Hb0[2][144];
    __shared__ __align__(16) float Hb1[2][144];
    __shared__ __align__(16) float Gs[3][ROWS * 2];

    const int g   = blockIdx.x >> 4;
    const int bp  = blockIdx.x & 15;
    const int tid = threadIdx.x;
    const int j   = tid >> 2;
    const int q   = tid & 3;
    const int b0  = bp * 2;

    ull wr[16], wz[16], wn[16];
    {
        const float* base = W_hh + (size_t)g * ROWS * 128 + q * 32;
        const float* pr = base + (size_t)(j)       * 128;
        const float* pz = base + (size_t)(128 + j) * 128;
        const float* pn = base + (size_t)(256 + j) * 128;
#pragma unroll
        for (int i = 0; i < 8; i++) {
            ulonglong2 a = *(const ulonglong2*)(pr + i * 4);
            wr[2 * i] = a.x; wr[2 * i + 1] = a.y;
            ulonglong2 b = *(const ulonglong2*)(pz + i * 4);
            wz[2 * i] = b.x; wz[2 * i + 1] = b.y;
            ulonglong2 c = *(const ulonglong2*)(pn + i * 4);
            wn[2 * i] = c.x; wn[2 * i + 1] = c.y;
        }
    }

    const float bhr = b_hh[g * ROWS + j];
    const float bhz = b_hh[g * ROWS + 128 + j];
    const float bhn = b_hh[g * ROWS + 256 + j];

    const int jsw = (j >> 5) * 36 + (j & 31);

    if (q == 0) Hb0[0][jsw] = state[((size_t)g * 32 + b0) * 128 + j];
    if (q == 1) Hb1[0][jsw] = state[((size_t)g * 32 + b0 + 1) * 128 + j];

    const size_t stride_t = (size_t)GR * ROWS * BATCH;
    const float* gx0 = g_gx + (size_t)g * ROWS * BATCH + b0;

    const float* gxt = gx0 + (size_t)tid * BATCH;
    if (tid < ROWS) cpa8(sptr(&Gs[0][tid * 2]), gxt);
    cpcommit();
    if (tid < ROWS) cpa8(sptr(&Gs[1][tid * 2]), gxt + stride_t);
    cpcommit();
    gxt += 2 * stride_t;
    cpwait1();
    __syncthreads();

    const int myb = q >> 1;
    float* outp = out + ((size_t)(b0 + myb) * TT) * 1024 + g * 128 + j;

    const int qoff = q * 36;
    int p = 0, cb = 0;

    for (int t = 0; t < TT; t++) {
        {
            int nb = cb + 2; if (nb >= 3) nb -= 3;
            if (t + 2 < TT && tid < ROWS)
                cpa8(sptr(&Gs[nb][tid * 2]), gxt);
            cpcommit();
            gxt += stride_t;
        }

        const float* H0 = Hb0[p];
        const float* H1 = Hb1[p];

        ull ar0 = 0, az0 = 0, an0 = 0;
        ull ar1 = 0, az1 = 0, an1 = 0;

#pragma unroll
        for (int i = 0; i < 8; i++) {
            ulonglong2 h0 = *(const ulonglong2*)(H0 + qoff + i * 4);
            ulonglong2 h1 = *(const ulonglong2*)(H1 + qoff + i * 4);
            fma2(ar0, wr[2 * i],     h0.x);
            fma2(az0, wz[2 * i],     h0.x);
            fma2(an0, wn[2 * i],     h0.x);
            fma2(ar1, wr[2 * i],     h1.x);
            fma2(az1, wz[2 * i],     h1.x);
            fma2(an1, wn[2 * i],     h1.x);
            fma2(ar0, wr[2 * i + 1], h0.y);
            fma2(az0, wz[2 * i + 1], h0.y);
            fma2(an0, wn[2 * i + 1], h0.y);
            fma2(ar1, wr[2 * i + 1], h1.y);
            fma2(az1, wz[2 * i + 1], h1.y);
            fma2(an1, wn[2 * i + 1], h1.y);
        }

        float sr0 = hadd(ar0), sz0 = hadd(az0), sn0 = hadd(an0);
        float sr1 = hadd(ar1), sz1 = hadd(az1), sn1 = hadd(an1);

        const bool hi = (q & 2) != 0;
        float vr = hi ? sr0 : sr1;
        float vz = hi ? sz0 : sz1;
        float vn = hi ? sn0 : sn1;
        float kr = hi ? sr1 : sr0;
        float kz = hi ? sz1 : sz0;
        float kn = hi ? sn1 : sn0;
        kr += __shfl_xor_sync(0xffffffffu, vr, 2);
        kz += __shfl_xor_sync(0xffffffffu, vz, 2);
        kn += __shfl_xor_sync(0xffffffffu, vn, 2);
        kr += __shfl_xor_sync(0xffffffffu, kr, 1);
        kz += __shfl_xor_sync(0xffffffffu, kz, 1);
        kn += __shfl_xor_sync(0xffffffffu, kn, 1);

        const float* Gc = Gs[cb];
        float gr_ = Gc[(j)       * 2 + myb];
        float gz_ = Gc[(128 + j) * 2 + myb];
        float gn_ = Gc[(256 + j) * 2 + myb];
        float hold = (hi ? H1 : H0)[jsw];

        float rr = sigm(gr_ + kr + bhr);
        float zz = sigm(gz_ + kz + bhz);
        float nn = tanh_(gn_ + rr * (kn + bhn));
        float hn = nn + zz * (hold - nn);

        const int np = p ^ 1;
        if (q == 0) {
            Hb0[np][jsw] = hn;
        } else if (q == 2) {
            Hb1[np][jsw] = hn;
        } else {
            *outp = hn;
        }
        outp += 1024;

        cpwait1();
        __syncthreads();
        p = np;
        cb = cb + 1; if (cb >= 3) cb -= 3;
    }

    float* hop = out + (size_t)BATCH * TT * 1024;
    if (q == 0) hop[((size_t)g * 32 + b0) * 128 + j]     = Hb0[p][jsw];
    if (q == 2) hop[((size_t)g * 32 + b0 + 1) * 128 + j] = Hb1[p][jsw];
}

extern "C" void kernel_launch(void* const* d_in, const int* in_sizes, int n_in,
                              void* d_out, int out_size)
{
    const float* x     = (const float*)d_in[0];
    const float* state = (const float*)d_in[1];
    const float* W_ih  = (const float*)d_in[2];
    const float* W_hh  = (const float*)d_in[3];
    const float* b_ih  = (const float*)d_in[4];
    const float* b_hh  = (const float*)d_in[5];
    float* out = (float*)d_out;

    const int smem_mma = A_SM_BYTES + 2 * B_SM_BYTES;   // 200,704
    cudaFuncSetAttribute(gx_mma, cudaFuncAttributeMaxDynamicSharedMemorySize, smem_mma);

    prep_w<<<1536, 256>>>(W_ih);
    gx_mma<<<384, 256, smem_mma>>>(x, b_ih);
    gru_kernel<<<128, 512>>>(state, W_hh, b_hh, out);
}